// round 1
// baseline (speedup 1.0000x reference)
#include <cuda_runtime.h>
#include <math.h>

#define SEQ 3072
#define HIDDEN 1280
#define NH 16
#define HD 80
#define RD 40
#define QKV_N (3 * HIDDEN)

// Scratch (allocation-free rule: __device__ globals)
__device__ float g_qkv[SEQ * QKV_N];    // [seq, 3*HIDDEN] : q|k|v interleaved per row
__device__ float g_att[SEQ * HIDDEN];   // attention output [seq, hidden]

// ---------------------------------------------------------------------------
// SGEMM: C[M,N] = A[M,K] @ B[K,N] + bias[N]
// BM=BN=128, BK=8, 256 threads, 8x8 per thread with split-64 layout.
// Requires M%128==0, N%128==0, K%8==0 (true for all three GEMMs here).
// ---------------------------------------------------------------------------
__global__ __launch_bounds__(256) void sgemm_bias(
    const float* __restrict__ A, const float* __restrict__ B,
    const float* __restrict__ bias, float* __restrict__ C,
    int M, int N, int K)
{
    __shared__ float As[8][128];
    __shared__ float Bs[8][128];

    const int tid = threadIdx.x;
    const int tx = tid & 15;        // 0..15 (cols)
    const int ty = tid >> 4;        // 0..15 (rows)
    const int m0 = blockIdx.y * 128;
    const int n0 = blockIdx.x * 128;

    float acc[8][8];
    #pragma unroll
    for (int i = 0; i < 8; i++)
        #pragma unroll
        for (int j = 0; j < 8; j++) acc[i][j] = 0.f;

    // loader coords
    const int a_r = tid >> 1;              // 0..127
    const int a_c = (tid & 1) * 4;         // 0 or 4
    const int b_r = tid >> 5;              // 0..7
    const int b_c = (tid & 31) * 4;        // 0..124

    for (int k0 = 0; k0 < K; k0 += 8) {
        // A tile 128x8 (stored transposed As[k][m])
        {
            float4 v = *reinterpret_cast<const float4*>(&A[(m0 + a_r) * K + k0 + a_c]);
            As[a_c + 0][a_r] = v.x;
            As[a_c + 1][a_r] = v.y;
            As[a_c + 2][a_r] = v.z;
            As[a_c + 3][a_r] = v.w;
        }
        // B tile 8x128
        {
            float4 v = *reinterpret_cast<const float4*>(&B[(k0 + b_r) * N + n0 + b_c]);
            *reinterpret_cast<float4*>(&Bs[b_r][b_c]) = v;
        }
        __syncthreads();

        #pragma unroll
        for (int k = 0; k < 8; k++) {
            float ra[8], rb[8];
            float4 a0 = *reinterpret_cast<const float4*>(&As[k][ty * 4]);
            float4 a1 = *reinterpret_cast<const float4*>(&As[k][64 + ty * 4]);
            float4 b0 = *reinterpret_cast<const float4*>(&Bs[k][tx * 4]);
            float4 b1 = *reinterpret_cast<const float4*>(&Bs[k][64 + tx * 4]);
            ra[0]=a0.x; ra[1]=a0.y; ra[2]=a0.z; ra[3]=a0.w;
            ra[4]=a1.x; ra[5]=a1.y; ra[6]=a1.z; ra[7]=a1.w;
            rb[0]=b0.x; rb[1]=b0.y; rb[2]=b0.z; rb[3]=b0.w;
            rb[4]=b1.x; rb[5]=b1.y; rb[6]=b1.z; rb[7]=b1.w;
            #pragma unroll
            for (int i = 0; i < 8; i++)
                #pragma unroll
                for (int j = 0; j < 8; j++)
                    acc[i][j] = fmaf(ra[i], rb[j], acc[i][j]);
        }
        __syncthreads();
    }

    // epilogue: rows split {ty*4+i, 64+ty*4+i}, cols split {tx*4+j, 64+tx*4+j}
    #pragma unroll
    for (int i = 0; i < 8; i++) {
        int m = m0 + ((i < 4) ? (ty * 4 + i) : (64 + ty * 4 + i - 4));
        int n_a = n0 + tx * 4;
        int n_b = n0 + 64 + tx * 4;
        int ja = (i, 0);  // dummy to keep structure clear
        (void)ja;
        float4 va, vb;
        va.x = acc[i][0] + bias[n_a + 0];
        va.y = acc[i][1] + bias[n_a + 1];
        va.z = acc[i][2] + bias[n_a + 2];
        va.w = acc[i][3] + bias[n_a + 3];
        vb.x = acc[i][4] + bias[n_b + 0];
        vb.y = acc[i][5] + bias[n_b + 1];
        vb.z = acc[i][6] + bias[n_b + 2];
        vb.w = acc[i][7] + bias[n_b + 3];
        *reinterpret_cast<float4*>(&C[m * N + n_a]) = va;
        *reinterpret_cast<float4*>(&C[m * N + n_b]) = vb;
    }
}

// ---------------------------------------------------------------------------
// RoPE (in place on q and k inside g_qkv).
// One thread per rotation pair (t, s in {q,k}, h, d<40).
// ---------------------------------------------------------------------------
__global__ __launch_bounds__(256) void rope_kernel(float* __restrict__ qkv,
                                                   const int* __restrict__ pos)
{
    const int total = SEQ * 2 * NH * RD;
    for (int idx = blockIdx.x * blockDim.x + threadIdx.x; idx < total;
         idx += gridDim.x * blockDim.x) {
        int d = idx % RD;
        int h = (idx / RD) % NH;
        int s = (idx / (RD * NH)) & 1;     // 0 = q, 1 = k
        int t = idx / (RD * NH * 2);

        int i = (d < 20) ? d : (d - 20);
        float p = (float)((d < 20) ? pos[t * 2 + 0] : pos[t * 2 + 1]);
        float inv_freq = powf(10000.0f, -(float)i / 20.0f);
        float ang = p * inv_freq;
        float sv, cv;
        sincosf(ang, &sv, &cv);

        int base = t * QKV_N + s * HIDDEN + h * HD;
        float x0 = qkv[base + d];
        float x1 = qkv[base + d + RD];
        qkv[base + d]      = x0 * cv - x1 * sv;
        qkv[base + d + RD] = x1 * cv + x0 * sv;
    }
}

// ---------------------------------------------------------------------------
// Flash-style attention. Grid: (SEQ/64, NH). 256 threads.
// Dynamic smem: sQ[64][81] + sKV[64][81] + sP[64][65]  = 58112 bytes.
// ---------------------------------------------------------------------------
#define SQ_(r,c)  sQ[(r) * 81 + (c)]
#define SK_(r,c)  sKV[(r) * 81 + (c)]
#define SP_(r,c)  sP[(r) * 65 + (c)]

__global__ __launch_bounds__(256) void attn_kernel()
{
    extern __shared__ float smem[];
    float* sQ  = smem;
    float* sKV = smem + 64 * 81;
    float* sP  = smem + 2 * 64 * 81;

    const int h  = blockIdx.y;
    const int q0 = blockIdx.x * 64;
    const int tid = threadIdx.x;
    const int tx = tid & 15;   // 0..15
    const int ty = tid >> 4;   // 0..15
    const float scale = 0.1118033988749895f;  // 80^-0.5

    // Load Q tile (pre-scaled)
    for (int i = tid; i < 64 * HD; i += 256) {
        int r = i / HD, c = i - r * HD;
        SQ_(r, c) = g_qkv[(q0 + r) * QKV_N + h * HD + c] * scale;
    }

    float mrow[4], lrow[4], acc[4][5];
    #pragma unroll
    for (int i = 0; i < 4; i++) {
        mrow[i] = -1e30f;
        lrow[i] = 0.f;
        #pragma unroll
        for (int j = 0; j < 5; j++) acc[i][j] = 0.f;
    }

    for (int k0 = 0; k0 < SEQ; k0 += 64) {
        __syncthreads();   // previous PV reads of sKV done; first iter: Q visible too
        // Load K tile
        for (int i = tid; i < 64 * HD; i += 256) {
            int r = i / HD, c = i - r * HD;
            SK_(r, c) = g_qkv[(k0 + r) * QKV_N + HIDDEN + h * HD + c];
        }
        __syncthreads();

        // S = Q @ K^T  (per-thread 4x4)
        float s[4][4];
        #pragma unroll
        for (int i = 0; i < 4; i++)
            #pragma unroll
            for (int j = 0; j < 4; j++) s[i][j] = 0.f;

        for (int d = 0; d < HD; d++) {
            float qa[4], kb[4];
            #pragma unroll
            for (int i = 0; i < 4; i++) qa[i] = SQ_(ty * 4 + i, d);
            #pragma unroll
            for (int j = 0; j < 4; j++) kb[j] = SK_(tx * 4 + j, d);
            #pragma unroll
            for (int i = 0; i < 4; i++)
                #pragma unroll
                for (int j = 0; j < 4; j++)
                    s[i][j] = fmaf(qa[i], kb[j], s[i][j]);
        }

        // Online softmax update (row spans 16 lanes of same ty within warp)
        #pragma unroll
        for (int i = 0; i < 4; i++) {
            float tm = fmaxf(fmaxf(s[i][0], s[i][1]), fmaxf(s[i][2], s[i][3]));
            #pragma unroll
            for (int o = 8; o > 0; o >>= 1)
                tm = fmaxf(tm, __shfl_xor_sync(0xffffffffu, tm, o));
            float mn = fmaxf(mrow[i], tm);
            float corr = __expf(mrow[i] - mn);
            mrow[i] = mn;
            float rs = 0.f;
            #pragma unroll
            for (int j = 0; j < 4; j++) {
                float p = __expf(s[i][j] - mn);
                SP_(ty * 4 + i, tx * 4 + j) = p;
                rs += p;
            }
            #pragma unroll
            for (int o = 8; o > 0; o >>= 1)
                rs += __shfl_xor_sync(0xffffffffu, rs, o);
            lrow[i] = lrow[i] * corr + rs;
            #pragma unroll
            for (int j = 0; j < 5; j++) acc[i][j] *= corr;
        }
        __syncthreads();   // sP visible; everyone done reading K

        // Load V tile (reuse sKV)
        for (int i = tid; i < 64 * HD; i += 256) {
            int r = i / HD, c = i - r * HD;
            SK_(r, c) = g_qkv[(k0 + r) * QKV_N + 2 * HIDDEN + h * HD + c];
        }
        __syncthreads();

        // O += P @ V   (per-thread 4 rows x 5 cols)
        #pragma unroll 4
        for (int c = 0; c < 64; c++) {
            float pv[4], vv[5];
            #pragma unroll
            for (int i = 0; i < 4; i++) pv[i] = SP_(ty * 4 + i, c);
            #pragma unroll
            for (int j = 0; j < 5; j++) vv[j] = SK_(c, tx * 5 + j);
            #pragma unroll
            for (int i = 0; i < 4; i++)
                #pragma unroll
                for (int j = 0; j < 5; j++)
                    acc[i][j] = fmaf(pv[i], vv[j], acc[i][j]);
        }
    }

    // Write normalized output
    #pragma unroll
    for (int i = 0; i < 4; i++) {
        int q = q0 + ty * 4 + i;
        float inv = 1.0f / lrow[i];
        #pragma unroll
        for (int j = 0; j < 5; j++)
            g_att[q * HIDDEN + h * HD + tx * 5 + j] = acc[i][j] * inv;
    }
}

// ---------------------------------------------------------------------------
extern "C" void kernel_launch(void* const* d_in, const int* in_sizes, int n_in,
                              void* d_out, int out_size)
{
    const float* hs    = (const float*)d_in[0];
    const int*   pos   = (const int*)d_in[1];
    const float* qkv_w = (const float*)d_in[2];
    const float* qkv_b = (const float*)d_in[3];
    const float* o_w   = (const float*)d_in[4];
    const float* o_b   = (const float*)d_in[5];
    float* out = (float*)d_out;

    float* qkv_ptr = nullptr;
    float* att_ptr = nullptr;
    cudaGetSymbolAddress((void**)&qkv_ptr, g_qkv);
    cudaGetSymbolAddress((void**)&att_ptr, g_att);

    const int attn_smem = (2 * 64 * 81 + 64 * 65) * (int)sizeof(float);  // 58112
    cudaFuncSetAttribute(attn_kernel, cudaFuncAttributeMaxDynamicSharedMemorySize,
                         attn_smem);

    // 1) QKV GEMM + bias : [3072,1280] @ [1280,3840]
    {
        dim3 grid(QKV_N / 128, SEQ / 128);  // (30, 24)
        sgemm_bias<<<grid, 256>>>(hs, qkv_w, qkv_b, qkv_ptr, SEQ, QKV_N, HIDDEN);
    }
    // 2) RoPE on q and k (in place)
    {
        int total = SEQ * 2 * NH * RD;
        rope_kernel<<<(total + 255) / 256, 256>>>(qkv_ptr, pos);
    }
    // 3) Attention
    {
        dim3 grid(SEQ / 64, NH);  // (48, 16)
        attn_kernel<<<grid, 256, attn_smem>>>();
    }
    // 4) O GEMM + bias : [3072,1280] @ [1280,1280]
    {
        dim3 grid(HIDDEN / 128, SEQ / 128);  // (10, 24)
        sgemm_bias<<<grid, 256>>>(att_ptr, o_w, o_b, out, SEQ, HIDDEN, HIDDEN);
    }
}

// round 2
// speedup vs baseline: 1.7904x; 1.7904x over previous
#include <cuda_runtime.h>
#include <math.h>
#include <stdint.h>

#define SEQ 3072
#define HIDDEN 1280
#define NH 16
#define HD 80
#define RD 40
#define QKV_N (3 * HIDDEN)

// Scratch (allocation-free rule: __device__ globals)
__device__ float g_qkv[SEQ * QKV_N];    // [seq, 3*HIDDEN] : q|k|v per row
__device__ float g_att[SEQ * HIDDEN];   // attention output [seq, hidden]

// ---------------------------------------------------------------------------
// tf32 helpers
// ---------------------------------------------------------------------------
__device__ __forceinline__ float tf32_rna(float x) {
    uint32_t u;
    asm("cvt.rna.tf32.f32 %0, %1;" : "=r"(u) : "f"(x));
    return __uint_as_float(u);
}

__device__ __forceinline__ void mma_tf32(float* d, const uint32_t* a,
                                         const uint32_t* b, const float* c) {
    asm volatile(
        "mma.sync.aligned.m16n8k8.row.col.f32.tf32.tf32.f32 "
        "{%0,%1,%2,%3},{%4,%5,%6,%7},{%8,%9},{%10,%11,%12,%13};"
        : "=f"(d[0]), "=f"(d[1]), "=f"(d[2]), "=f"(d[3])
        : "r"(a[0]), "r"(a[1]), "r"(a[2]), "r"(a[3]),
          "r"(b[0]), "r"(b[1]),
          "f"(c[0]), "f"(c[1]), "f"(c[2]), "f"(c[3]));
}

// ---------------------------------------------------------------------------
// SGEMM: C[M,N] = A[M,K] @ B[K,N] + bias[N]  (unchanged from round 1)
// ---------------------------------------------------------------------------
__global__ __launch_bounds__(256) void sgemm_bias(
    const float* __restrict__ A, const float* __restrict__ B,
    const float* __restrict__ bias, float* __restrict__ C,
    int M, int N, int K)
{
    __shared__ float As[8][128];
    __shared__ float Bs[8][128];

    const int tid = threadIdx.x;
    const int tx = tid & 15;
    const int ty = tid >> 4;
    const int m0 = blockIdx.y * 128;
    const int n0 = blockIdx.x * 128;

    float acc[8][8];
    #pragma unroll
    for (int i = 0; i < 8; i++)
        #pragma unroll
        for (int j = 0; j < 8; j++) acc[i][j] = 0.f;

    const int a_r = tid >> 1;
    const int a_c = (tid & 1) * 4;
    const int b_r = tid >> 5;
    const int b_c = (tid & 31) * 4;

    for (int k0 = 0; k0 < K; k0 += 8) {
        {
            float4 v = *reinterpret_cast<const float4*>(&A[(m0 + a_r) * K + k0 + a_c]);
            As[a_c + 0][a_r] = v.x;
            As[a_c + 1][a_r] = v.y;
            As[a_c + 2][a_r] = v.z;
            As[a_c + 3][a_r] = v.w;
        }
        {
            float4 v = *reinterpret_cast<const float4*>(&B[(k0 + b_r) * N + n0 + b_c]);
            *reinterpret_cast<float4*>(&Bs[b_r][b_c]) = v;
        }
        __syncthreads();

        #pragma unroll
        for (int k = 0; k < 8; k++) {
            float ra[8], rb[8];
            float4 a0 = *reinterpret_cast<const float4*>(&As[k][ty * 4]);
            float4 a1 = *reinterpret_cast<const float4*>(&As[k][64 + ty * 4]);
            float4 b0 = *reinterpret_cast<const float4*>(&Bs[k][tx * 4]);
            float4 b1 = *reinterpret_cast<const float4*>(&Bs[k][64 + tx * 4]);
            ra[0]=a0.x; ra[1]=a0.y; ra[2]=a0.z; ra[3]=a0.w;
            ra[4]=a1.x; ra[5]=a1.y; ra[6]=a1.z; ra[7]=a1.w;
            rb[0]=b0.x; rb[1]=b0.y; rb[2]=b0.z; rb[3]=b0.w;
            rb[4]=b1.x; rb[5]=b1.y; rb[6]=b1.z; rb[7]=b1.w;
            #pragma unroll
            for (int i = 0; i < 8; i++)
                #pragma unroll
                for (int j = 0; j < 8; j++)
                    acc[i][j] = fmaf(ra[i], rb[j], acc[i][j]);
        }
        __syncthreads();
    }

    #pragma unroll
    for (int i = 0; i < 8; i++) {
        int m = m0 + ((i < 4) ? (ty * 4 + i) : (64 + ty * 4 + i - 4));
        int n_a = n0 + tx * 4;
        int n_b = n0 + 64 + tx * 4;
        float4 va, vb;
        va.x = acc[i][0] + bias[n_a + 0];
        va.y = acc[i][1] + bias[n_a + 1];
        va.z = acc[i][2] + bias[n_a + 2];
        va.w = acc[i][3] + bias[n_a + 3];
        vb.x = acc[i][4] + bias[n_b + 0];
        vb.y = acc[i][5] + bias[n_b + 1];
        vb.z = acc[i][6] + bias[n_b + 2];
        vb.w = acc[i][7] + bias[n_b + 3];
        *reinterpret_cast<float4*>(&C[m * N + n_a]) = va;
        *reinterpret_cast<float4*>(&C[m * N + n_b]) = vb;
    }
}

// ---------------------------------------------------------------------------
// RoPE (in place on q and k inside g_qkv).
// ---------------------------------------------------------------------------
__global__ __launch_bounds__(256) void rope_kernel(float* __restrict__ qkv,
                                                   const int* __restrict__ pos)
{
    const int total = SEQ * 2 * NH * RD;
    for (int idx = blockIdx.x * blockDim.x + threadIdx.x; idx < total;
         idx += gridDim.x * blockDim.x) {
        int d = idx % RD;
        int h = (idx / RD) % NH;
        int s = (idx / (RD * NH)) & 1;
        int t = idx / (RD * NH * 2);

        int i = (d < 20) ? d : (d - 20);
        float p = (float)((d < 20) ? pos[t * 2 + 0] : pos[t * 2 + 1]);
        float inv_freq = powf(10000.0f, -(float)i / 20.0f);
        float ang = p * inv_freq;
        float sv, cv;
        sincosf(ang, &sv, &cv);

        int base = t * QKV_N + s * HIDDEN + h * HD;
        float x0 = qkv[base + d];
        float x1 = qkv[base + d + RD];
        qkv[base + d]      = x0 * cv - x1 * sv;
        qkv[base + d + RD] = x1 * cv + x0 * sv;
    }
}

// ---------------------------------------------------------------------------
// Flash attention with mma.sync m16n8k8 tf32.
// Grid (SEQ/64, NH), 128 threads (4 warps; warp w owns q-rows 16w..16w+15).
// smem: sQ 64x84 (aliased as sP 64x68 after Q frags are register-resident),
//       sK 64x84, sV 64x88  = 65536 bytes -> 3 CTAs/SM.
// ---------------------------------------------------------------------------
#define LDQ 84
#define LDK 84
#define LDV 88
#define LDP 68

__global__ __launch_bounds__(128, 3) void attn_kernel()
{
    extern __shared__ float smem[];
    float* sQ = smem;                       // 64 x LDQ
    float* sK = smem + 64 * LDQ;            // 64 x LDK
    float* sV = smem + 64 * (LDQ + LDK);    // 64 x LDV
    float* sP = sQ;                         // alias, 64 x LDP

    const int h   = blockIdx.y;
    const int q0  = blockIdx.x * 64;
    const int tid = threadIdx.x;
    const int w    = tid >> 5;
    const int lane = tid & 31;
    const int gid  = lane >> 2;   // 0..7
    const int tig  = lane & 3;    // 0..3
    const float scale = 0.11180339887498949f;  // 80^-0.5

    // Stage Q (scaled + tf32-rounded)
    for (int i = tid; i < 64 * HD; i += 128) {
        int r = i / HD, c = i - r * HD;
        sQ[r * LDQ + c] = tf32_rna(g_qkv[(q0 + r) * QKV_N + h * HD + c] * scale);
    }
    __syncthreads();

    // Register-resident Q fragments: 10 k-steps x 4 regs
    uint32_t qa[10][4];
    const int qrow = 16 * w + gid;
    #pragma unroll
    for (int t = 0; t < 10; t++) {
        qa[t][0] = __float_as_uint(sQ[ qrow      * LDQ + t * 8 + tig]);
        qa[t][1] = __float_as_uint(sQ[(qrow + 8) * LDQ + t * 8 + tig]);
        qa[t][2] = __float_as_uint(sQ[ qrow      * LDQ + t * 8 + tig + 4]);
        qa[t][3] = __float_as_uint(sQ[(qrow + 8) * LDQ + t * 8 + tig + 4]);
    }
    __syncthreads();   // everyone done with sQ; it becomes sP

    float m0r = -1e30f, m1r = -1e30f, l0 = 0.f, l1 = 0.f;
    float acc[10][4];
    #pragma unroll
    for (int n = 0; n < 10; n++)
        #pragma unroll
        for (int j = 0; j < 4; j++) acc[n][j] = 0.f;

    for (int kt = 0; kt < SEQ / 64; kt++) {
        const int k0 = kt * 64;
        // Stage K and V (tf32-rounded)
        for (int i = tid; i < 64 * HD; i += 128) {
            int r = i / HD, c = i - r * HD;
            const float* src = &g_qkv[(k0 + r) * QKV_N + h * HD + c];
            sK[r * LDK + c] = tf32_rna(src[HIDDEN]);
            sV[r * LDV + c] = tf32_rna(src[2 * HIDDEN]);
        }
        __syncthreads();

        // S = Q @ K^T : 8 n-tiles (keys) x 10 k-steps (headdim)
        float sf[8][4];
        #pragma unroll
        for (int n = 0; n < 8; n++)
            #pragma unroll
            for (int j = 0; j < 4; j++) sf[n][j] = 0.f;

        #pragma unroll
        for (int t = 0; t < 10; t++) {
            #pragma unroll
            for (int n = 0; n < 8; n++) {
                uint32_t b[2];
                b[0] = __float_as_uint(sK[(n * 8 + gid) * LDK + t * 8 + tig]);
                b[1] = __float_as_uint(sK[(n * 8 + gid) * LDK + t * 8 + tig + 4]);
                mma_tf32(sf[n], qa[t], b, sf[n]);
            }
        }

        // Online softmax. Thread owns rows (16w+gid) [frag 0,1] and +8 [frag 2,3].
        float mx0 = -1e30f, mx1 = -1e30f;
        #pragma unroll
        for (int n = 0; n < 8; n++) {
            mx0 = fmaxf(mx0, fmaxf(sf[n][0], sf[n][1]));
            mx1 = fmaxf(mx1, fmaxf(sf[n][2], sf[n][3]));
        }
        #pragma unroll
        for (int o = 1; o <= 2; o <<= 1) {
            mx0 = fmaxf(mx0, __shfl_xor_sync(0xffffffffu, mx0, o));
            mx1 = fmaxf(mx1, __shfl_xor_sync(0xffffffffu, mx1, o));
        }
        float nm0 = fmaxf(m0r, mx0), nm1 = fmaxf(m1r, mx1);
        float c0 = __expf(m0r - nm0), c1 = __expf(m1r - nm1);
        m0r = nm0; m1r = nm1;

        float s0 = 0.f, s1 = 0.f;
        #pragma unroll
        for (int n = 0; n < 8; n++) {
            float p00 = __expf(sf[n][0] - nm0);
            float p01 = __expf(sf[n][1] - nm0);
            float p10 = __expf(sf[n][2] - nm1);
            float p11 = __expf(sf[n][3] - nm1);
            s0 += p00 + p01;
            s1 += p10 + p11;
            float2 v0 = make_float2(tf32_rna(p00), tf32_rna(p01));
            float2 v1 = make_float2(tf32_rna(p10), tf32_rna(p11));
            *reinterpret_cast<float2*>(&sP[(16 * w + gid)     * LDP + n * 8 + 2 * tig]) = v0;
            *reinterpret_cast<float2*>(&sP[(16 * w + gid + 8) * LDP + n * 8 + 2 * tig]) = v1;
        }
        #pragma unroll
        for (int o = 1; o <= 2; o <<= 1) {
            s0 += __shfl_xor_sync(0xffffffffu, s0, o);
            s1 += __shfl_xor_sync(0xffffffffu, s1, o);
        }
        l0 = l0 * c0 + s0;
        l1 = l1 * c1 + s1;
        #pragma unroll
        for (int n = 0; n < 10; n++) {
            acc[n][0] *= c0; acc[n][1] *= c0;
            acc[n][2] *= c1; acc[n][3] *= c1;
        }
        __syncwarp();  // P rows are warp-private; warp-level visibility suffices

        // O += P @ V : 8 k-steps (keys) x 10 n-tiles (headdim)
        #pragma unroll
        for (int s8 = 0; s8 < 8; s8++) {
            uint32_t pa[4];
            pa[0] = __float_as_uint(sP[ qrow      * LDP + s8 * 8 + tig]);
            pa[1] = __float_as_uint(sP[(qrow + 8) * LDP + s8 * 8 + tig]);
            pa[2] = __float_as_uint(sP[ qrow      * LDP + s8 * 8 + tig + 4]);
            pa[3] = __float_as_uint(sP[(qrow + 8) * LDP + s8 * 8 + tig + 4]);
            #pragma unroll
            for (int n = 0; n < 10; n++) {
                uint32_t b[2];
                b[0] = __float_as_uint(sV[(s8 * 8 + tig)     * LDV + n * 8 + gid]);
                b[1] = __float_as_uint(sV[(s8 * 8 + tig + 4) * LDV + n * 8 + gid]);
                mma_tf32(acc[n], pa, b, acc[n]);
            }
        }
        __syncthreads();  // done reading sK/sV before next tile overwrites
    }

    // Epilogue: normalize and store
    float i0 = 1.0f / l0, i1 = 1.0f / l1;
    #pragma unroll
    for (int n = 0; n < 10; n++) {
        int col = h * HD + n * 8 + 2 * tig;
        float2 v0 = make_float2(acc[n][0] * i0, acc[n][1] * i0);
        float2 v1 = make_float2(acc[n][2] * i1, acc[n][3] * i1);
        *reinterpret_cast<float2*>(&g_att[(q0 + 16 * w + gid)     * HIDDEN + col]) = v0;
        *reinterpret_cast<float2*>(&g_att[(q0 + 16 * w + gid + 8) * HIDDEN + col]) = v1;
    }
}

// ---------------------------------------------------------------------------
extern "C" void kernel_launch(void* const* d_in, const int* in_sizes, int n_in,
                              void* d_out, int out_size)
{
    const float* hs    = (const float*)d_in[0];
    const int*   pos   = (const int*)d_in[1];
    const float* qkv_w = (const float*)d_in[2];
    const float* qkv_b = (const float*)d_in[3];
    const float* o_w   = (const float*)d_in[4];
    const float* o_b   = (const float*)d_in[5];
    float* out = (float*)d_out;

    float* qkv_ptr = nullptr;
    float* att_ptr = nullptr;
    cudaGetSymbolAddress((void**)&qkv_ptr, g_qkv);
    cudaGetSymbolAddress((void**)&att_ptr, g_att);

    const int attn_smem = 64 * (LDQ + LDK + LDV) * (int)sizeof(float);  // 65536
    cudaFuncSetAttribute(attn_kernel, cudaFuncAttributeMaxDynamicSharedMemorySize,
                         attn_smem);

    // 1) QKV GEMM + bias
    {
        dim3 grid(QKV_N / 128, SEQ / 128);
        sgemm_bias<<<grid, 256>>>(hs, qkv_w, qkv_b, qkv_ptr, SEQ, QKV_N, HIDDEN);
    }
    // 2) RoPE
    {
        int total = SEQ * 2 * NH * RD;
        rope_kernel<<<(total + 255) / 256, 256>>>(qkv_ptr, pos);
    }
    // 3) Attention (tf32 tensor cores)
    {
        dim3 grid(SEQ / 64, NH);
        attn_kernel<<<grid, 128, attn_smem>>>();
    }
    // 4) O GEMM + bias
    {
        dim3 grid(HIDDEN / 128, SEQ / 128);
        sgemm_bias<<<grid, 256>>>(att_ptr, o_w, o_b, out, SEQ, HIDDEN, HIDDEN);
    }
}

// round 4
// speedup vs baseline: 2.4461x; 1.3662x over previous
#include <cuda_runtime.h>
#include <cuda_fp16.h>
#include <math.h>
#include <stdint.h>

#define SEQ 3072
#define HIDDEN 1280
#define NH 16
#define HD 80
#define RD 40
#define QKV_N (3 * HIDDEN)

// Scratch (allocation-free rule: __device__ globals)
__device__ float g_qkv[SEQ * QKV_N];      // QKV GEMM output (fp32)
__device__ float g_att[SEQ * HIDDEN];     // attention output (fp32)
__device__ __half g_q16[NH * SEQ * HD];   // head-major, rope'd, pre-scaled
__device__ __half g_k16[NH * SEQ * HD];   // head-major, rope'd
__device__ __half g_v16[NH * SEQ * HD];   // head-major

// ---------------------------------------------------------------------------
// helpers
// ---------------------------------------------------------------------------
__device__ __forceinline__ uint32_t h2_as_u32(__half2 h) {
    union { __half2 h2; uint32_t u; } cvt;
    cvt.h2 = h;
    return cvt.u;
}

__device__ __forceinline__ void mma_f16(float* d, const uint32_t* a, const uint32_t* b) {
    asm volatile(
        "mma.sync.aligned.m16n8k16.row.col.f32.f16.f16.f32 "
        "{%0,%1,%2,%3},{%4,%5,%6,%7},{%8,%9},{%0,%1,%2,%3};"
        : "+f"(d[0]), "+f"(d[1]), "+f"(d[2]), "+f"(d[3])
        : "r"(a[0]), "r"(a[1]), "r"(a[2]), "r"(a[3]),
          "r"(b[0]), "r"(b[1]));
}

__device__ __forceinline__ void ldsm_x4(uint32_t* r, uint32_t addr) {
    asm volatile("ldmatrix.sync.aligned.m8n8.x4.shared.b16 {%0,%1,%2,%3},[%4];"
        : "=r"(r[0]), "=r"(r[1]), "=r"(r[2]), "=r"(r[3]) : "r"(addr));
}

__device__ __forceinline__ void ldsm_x4_t(uint32_t* r, uint32_t addr) {
    asm volatile("ldmatrix.sync.aligned.m8n8.x4.trans.shared.b16 {%0,%1,%2,%3},[%4];"
        : "=r"(r[0]), "=r"(r[1]), "=r"(r[2]), "=r"(r[3]) : "r"(addr));
}

// ---------------------------------------------------------------------------
// SGEMM: C[M,N] = A[M,K] @ B[K,N] + bias[N]  (unchanged)
// ---------------------------------------------------------------------------
__global__ __launch_bounds__(256) void sgemm_bias(
    const float* __restrict__ A, const float* __restrict__ B,
    const float* __restrict__ bias, float* __restrict__ C,
    int M, int N, int K)
{
    __shared__ float As[8][128];
    __shared__ float Bs[8][128];

    const int tid = threadIdx.x;
    const int tx = tid & 15;
    const int ty = tid >> 4;
    const int m0 = blockIdx.y * 128;
    const int n0 = blockIdx.x * 128;

    float acc[8][8];
    #pragma unroll
    for (int i = 0; i < 8; i++)
        #pragma unroll
        for (int j = 0; j < 8; j++) acc[i][j] = 0.f;

    const int a_r = tid >> 1;
    const int a_c = (tid & 1) * 4;
    const int b_r = tid >> 5;
    const int b_c = (tid & 31) * 4;

    for (int k0 = 0; k0 < K; k0 += 8) {
        {
            float4 v = *reinterpret_cast<const float4*>(&A[(m0 + a_r) * K + k0 + a_c]);
            As[a_c + 0][a_r] = v.x;
            As[a_c + 1][a_r] = v.y;
            As[a_c + 2][a_r] = v.z;
            As[a_c + 3][a_r] = v.w;
        }
        {
            float4 v = *reinterpret_cast<const float4*>(&B[(k0 + b_r) * N + n0 + b_c]);
            *reinterpret_cast<float4*>(&Bs[b_r][b_c]) = v;
        }
        __syncthreads();

        #pragma unroll
        for (int k = 0; k < 8; k++) {
            float ra[8], rb[8];
            float4 a0 = *reinterpret_cast<const float4*>(&As[k][ty * 4]);
            float4 a1 = *reinterpret_cast<const float4*>(&As[k][64 + ty * 4]);
            float4 b0 = *reinterpret_cast<const float4*>(&Bs[k][tx * 4]);
            float4 b1 = *reinterpret_cast<const float4*>(&Bs[k][64 + tx * 4]);
            ra[0]=a0.x; ra[1]=a0.y; ra[2]=a0.z; ra[3]=a0.w;
            ra[4]=a1.x; ra[5]=a1.y; ra[6]=a1.z; ra[7]=a1.w;
            rb[0]=b0.x; rb[1]=b0.y; rb[2]=b0.z; rb[3]=b0.w;
            rb[4]=b1.x; rb[5]=b1.y; rb[6]=b1.z; rb[7]=b1.w;
            #pragma unroll
            for (int i = 0; i < 8; i++)
                #pragma unroll
                for (int j = 0; j < 8; j++)
                    acc[i][j] = fmaf(ra[i], rb[j], acc[i][j]);
        }
        __syncthreads();
    }

    #pragma unroll
    for (int i = 0; i < 8; i++) {
        int m = m0 + ((i < 4) ? (ty * 4 + i) : (64 + ty * 4 + i - 4));
        int n_a = n0 + tx * 4;
        int n_b = n0 + 64 + tx * 4;
        float4 va, vb;
        va.x = acc[i][0] + bias[n_a + 0];
        va.y = acc[i][1] + bias[n_a + 1];
        va.z = acc[i][2] + bias[n_a + 2];
        va.w = acc[i][3] + bias[n_a + 3];
        vb.x = acc[i][4] + bias[n_b + 0];
        vb.y = acc[i][5] + bias[n_b + 1];
        vb.z = acc[i][6] + bias[n_b + 2];
        vb.w = acc[i][7] + bias[n_b + 3];
        *reinterpret_cast<float4*>(&C[m * N + n_a]) = va;
        *reinterpret_cast<float4*>(&C[m * N + n_b]) = vb;
    }
}

// ---------------------------------------------------------------------------
// RoPE + fp16 convert for Q and K (head-major output). Q pre-scaled.
// ---------------------------------------------------------------------------
__global__ __launch_bounds__(256) void rope_cvt(const float* __restrict__ qkv,
                                                const int* __restrict__ pos)
{
    const int total = SEQ * 2 * NH * RD;
    int idx = blockIdx.x * blockDim.x + threadIdx.x;
    if (idx >= total) return;

    int d = idx % RD;
    int h = (idx / RD) % NH;
    int s = (idx / (RD * NH)) & 1;     // 0 = q, 1 = k
    int t = idx / (RD * NH * 2);

    int i = (d < 20) ? d : (d - 20);
    float p = (float)pos[t * 2 + ((d < 20) ? 0 : 1)];
    // 10000^(-i/20) = 2^(-i * log2(10000)/20)
    float ang = p * exp2f(-0.66438561897747246f * (float)i);
    float sv, cv;
    sincosf(ang, &sv, &cv);

    const float* src = &qkv[t * QKV_N + s * HIDDEN + h * HD];
    float x0 = src[d];
    float x1 = src[d + RD];
    float y0 = x0 * cv - x1 * sv;
    float y1 = x1 * cv + x0 * sv;

    float sc = s ? 1.0f : 0.11180339887498949f;   // q pre-scaled by 80^-0.5
    __half* dst = s ? g_k16 : g_q16;
    dst[(h * SEQ + t) * HD + d]      = __float2half(y0 * sc);
    dst[(h * SEQ + t) * HD + d + RD] = __float2half(y1 * sc);
}

// ---------------------------------------------------------------------------
// V fp16 convert (head-major). One thread per float4.
// ---------------------------------------------------------------------------
__global__ __launch_bounds__(256) void v_cvt(const float* __restrict__ qkv)
{
    const int total = SEQ * NH * (HD / 4);
    int idx = blockIdx.x * blockDim.x + threadIdx.x;
    if (idx >= total) return;
    int c4 = idx % (HD / 4);
    int h  = (idx / (HD / 4)) % NH;
    int t  = idx / ((HD / 4) * NH);

    float4 v = *reinterpret_cast<const float4*>(
        &qkv[t * QKV_N + 2 * HIDDEN + h * HD + c4 * 4]);
    __half2* dst = reinterpret_cast<__half2*>(&g_v16[(h * SEQ + t) * HD + c4 * 4]);
    dst[0] = __floats2half2_rn(v.x, v.y);
    dst[1] = __floats2half2_rn(v.z, v.w);
}

// ---------------------------------------------------------------------------
// Flash attention, fp16 mma m16n8k16, P kept in registers.
// Grid (SEQ/64, NH), 128 threads. smem: sK[64][88] + sV[64][88] halves.
// ---------------------------------------------------------------------------
#define LDH 88   // halves per smem row (44 words; 12r mod 32 conflict-free)

__global__ __launch_bounds__(128, 4) void attn_kernel()
{
    __shared__ __half sK[64 * LDH];
    __shared__ __half sV[64 * LDH];

    const int h   = blockIdx.y;
    const int q0  = blockIdx.x * 64;
    const int tid = threadIdx.x;
    const int w    = tid >> 5;
    const int lane = tid & 31;
    const int gid  = lane >> 2;   // 0..7
    const int tig  = lane & 3;    // 0..3
    const int j8   = lane & 7;    // 0..7 (ldmatrix row-provider)
    const int grp  = lane >> 3;   // 0..3 (ldmatrix matrix id)

    const uint32_t skBase = (uint32_t)__cvta_generic_to_shared(sK);
    const uint32_t svBase = (uint32_t)__cvta_generic_to_shared(sV);
    // per-thread ldmatrix offsets (in halves)
    const int kOff = ((grp >> 1) * 8 + j8) * LDH + (grp & 1) * 8;  // K: non-trans
    const int vOff = ((grp & 1) * 8 + j8) * LDH + (grp >> 1) * 8;  // V: trans

    // ---- Stage Q tile into sK, extract register fragments ----
    {
        const __half* qg = &g_q16[(h * SEQ + q0) * HD];
        #pragma unroll
        for (int i = tid; i < 640; i += 128) {
            int r = i / 10, c = i % 10;
            *reinterpret_cast<uint4*>(&sK[r * LDH + c * 8]) =
                *reinterpret_cast<const uint4*>(&qg[r * HD + c * 8]);
        }
    }
    __syncthreads();

    uint32_t qa[5][4];
    const int qrow = 16 * w + gid;
    #pragma unroll
    for (int t = 0; t < 5; t++) {
        qa[t][0] = *reinterpret_cast<uint32_t*>(&sK[ qrow      * LDH + t * 16 + 2 * tig]);
        qa[t][1] = *reinterpret_cast<uint32_t*>(&sK[(qrow + 8) * LDH + t * 16 + 2 * tig]);
        qa[t][2] = *reinterpret_cast<uint32_t*>(&sK[ qrow      * LDH + t * 16 + 2 * tig + 8]);
        qa[t][3] = *reinterpret_cast<uint32_t*>(&sK[(qrow + 8) * LDH + t * 16 + 2 * tig + 8]);
    }

    float m0r = -1e30f, m1r = -1e30f, l0 = 0.f, l1 = 0.f;
    float acc[10][4];
    #pragma unroll
    for (int n = 0; n < 10; n++)
        #pragma unroll
        for (int jj = 0; jj < 4; jj++) acc[n][jj] = 0.f;

    for (int kt = 0; kt < SEQ / 64; kt++) {
        const int k0 = kt * 64;
        __syncthreads();   // prior tile reads done (and Q extraction at kt=0)

        // ---- Stage K and V tiles (straight fp16 copies) ----
        {
            const __half* kg = &g_k16[(h * SEQ + k0) * HD];
            const __half* vg = &g_v16[(h * SEQ + k0) * HD];
            #pragma unroll
            for (int i = tid; i < 640; i += 128) {
                int r = i / 10, c = i % 10;
                *reinterpret_cast<uint4*>(&sK[r * LDH + c * 8]) =
                    *reinterpret_cast<const uint4*>(&kg[r * HD + c * 8]);
                *reinterpret_cast<uint4*>(&sV[r * LDH + c * 8]) =
                    *reinterpret_cast<const uint4*>(&vg[r * HD + c * 8]);
            }
        }
        __syncthreads();

        // ---- S = Q @ K^T : 5 k-steps x 4 n-pairs ----
        float sf[8][4];
        #pragma unroll
        for (int n = 0; n < 8; n++)
            #pragma unroll
            for (int jj = 0; jj < 4; jj++) sf[n][jj] = 0.f;

        #pragma unroll
        for (int t = 0; t < 5; t++) {
            #pragma unroll
            for (int np = 0; np < 4; np++) {
                uint32_t b[4];
                ldsm_x4(b, skBase + (uint32_t)(np * 16 * LDH + t * 16 + kOff) * 2u);
                mma_f16(sf[2 * np],     qa[t], b);
                mma_f16(sf[2 * np + 1], qa[t], b + 2);
            }
        }

        // ---- Online softmax (rows gid / gid+8; reduce over tig via xor 1,2) ----
        float mx0 = -1e30f, mx1 = -1e30f;
        #pragma unroll
        for (int n = 0; n < 8; n++) {
            mx0 = fmaxf(mx0, fmaxf(sf[n][0], sf[n][1]));
            mx1 = fmaxf(mx1, fmaxf(sf[n][2], sf[n][3]));
        }
        #pragma unroll
        for (int o = 1; o <= 2; o <<= 1) {
            mx0 = fmaxf(mx0, __shfl_xor_sync(0xffffffffu, mx0, o));
            mx1 = fmaxf(mx1, __shfl_xor_sync(0xffffffffu, mx1, o));
        }
        float nm0 = fmaxf(m0r, mx0), nm1 = fmaxf(m1r, mx1);
        float c0 = __expf(m0r - nm0), c1 = __expf(m1r - nm1);
        m0r = nm0; m1r = nm1;

        float s0 = 0.f, s1 = 0.f;
        #pragma unroll
        for (int n = 0; n < 8; n++) {
            sf[n][0] = __expf(sf[n][0] - nm0);
            sf[n][1] = __expf(sf[n][1] - nm0);
            sf[n][2] = __expf(sf[n][2] - nm1);
            sf[n][3] = __expf(sf[n][3] - nm1);
            s0 += sf[n][0] + sf[n][1];
            s1 += sf[n][2] + sf[n][3];
        }
        #pragma unroll
        for (int o = 1; o <= 2; o <<= 1) {
            s0 += __shfl_xor_sync(0xffffffffu, s0, o);
            s1 += __shfl_xor_sync(0xffffffffu, s1, o);
        }
        l0 = l0 * c0 + s0;
        l1 = l1 * c1 + s1;
        #pragma unroll
        for (int n = 0; n < 10; n++) {
            acc[n][0] *= c0; acc[n][1] *= c0;
            acc[n][2] *= c1; acc[n][3] *= c1;
        }

        // ---- O += P @ V : P fragments come straight from sf (register trick) ----
        #pragma unroll
        for (int s = 0; s < 4; s++) {
            uint32_t pa[4];
            pa[0] = h2_as_u32(__floats2half2_rn(sf[2*s][0],   sf[2*s][1]));
            pa[1] = h2_as_u32(__floats2half2_rn(sf[2*s][2],   sf[2*s][3]));
            pa[2] = h2_as_u32(__floats2half2_rn(sf[2*s+1][0], sf[2*s+1][1]));
            pa[3] = h2_as_u32(__floats2half2_rn(sf[2*s+1][2], sf[2*s+1][3]));
            #pragma unroll
            for (int np = 0; np < 5; np++) {
                uint32_t b[4];
                ldsm_x4_t(b, svBase + (uint32_t)(s * 16 * LDH + np * 16 + vOff) * 2u);
                mma_f16(acc[2 * np],     pa, b);
                mma_f16(acc[2 * np + 1], pa, b + 2);
            }
        }
    }

    // ---- Epilogue: normalize and store fp32 ----
    float i0 = 1.0f / l0, i1 = 1.0f / l1;
    #pragma unroll
    for (int n = 0; n < 10; n++) {
        int col = h * HD + n * 8 + 2 * tig;
        float2 v0 = make_float2(acc[n][0] * i0, acc[n][1] * i0);
        float2 v1 = make_float2(acc[n][2] * i1, acc[n][3] * i1);
        *reinterpret_cast<float2*>(&g_att[(q0 + qrow)     * HIDDEN + col]) = v0;
        *reinterpret_cast<float2*>(&g_att[(q0 + qrow + 8) * HIDDEN + col]) = v1;
    }
}

// ---------------------------------------------------------------------------
extern "C" void kernel_launch(void* const* d_in, const int* in_sizes, int n_in,
                              void* d_out, int out_size)
{
    const float* hs    = (const float*)d_in[0];
    const int*   pos   = (const int*)d_in[1];
    const float* qkv_w = (const float*)d_in[2];
    const float* qkv_b = (const float*)d_in[3];
    const float* o_w   = (const float*)d_in[4];
    const float* o_b   = (const float*)d_in[5];
    float* out = (float*)d_out;

    float* qkv_ptr = nullptr;
    float* att_ptr = nullptr;
    cudaGetSymbolAddress((void**)&qkv_ptr, g_qkv);
    cudaGetSymbolAddress((void**)&att_ptr, g_att);

    // 1) QKV GEMM + bias
    {
        dim3 grid(QKV_N / 128, SEQ / 128);
        sgemm_bias<<<grid, 256>>>(hs, qkv_w, qkv_b, qkv_ptr, SEQ, QKV_N, HIDDEN);
    }
    // 2) RoPE + fp16 convert (q,k), fp16 convert (v)
    {
        int total = SEQ * 2 * NH * RD;
        rope_cvt<<<(total + 255) / 256, 256>>>(qkv_ptr, pos);
        int totv = SEQ * NH * (HD / 4);
        v_cvt<<<(totv + 255) / 256, 256>>>(qkv_ptr);
    }
    // 3) Attention (fp16 tensor cores, register-resident P)
    {
        dim3 grid(SEQ / 64, NH);
        attn_kernel<<<grid, 128>>>();
    }
    // 4) O GEMM + bias
    {
        dim3 grid(HIDDEN / 128, SEQ / 128);
        sgemm_bias<<<grid, 256>>>(att_ptr, o_w, o_b, out, SEQ, HIDDEN, HIDDEN);
    }
}

// round 5
// speedup vs baseline: 7.3941x; 3.0228x over previous
#include <cuda_runtime.h>
#include <cuda_fp16.h>
#include <math.h>
#include <stdint.h>

#define SEQ 3072
#define HIDDEN 1280
#define NH 16
#define HD 80
#define RD 40
#define QKV_N (3 * HIDDEN)

// Scratch (allocation-free rule: __device__ globals)
__device__ float  g_qkv[SEQ * QKV_N];       // QKV GEMM output (fp32)
__device__ __half g_hs16[SEQ * HIDDEN];     // hidden_states fp16
__device__ __half g_qw16[HIDDEN * QKV_N];   // qkv_w fp16
__device__ __half g_ow16[HIDDEN * HIDDEN];  // o_w fp16
__device__ __half g_att16[SEQ * HIDDEN];    // attention output fp16
__device__ __half g_q16[NH * SEQ * HD];     // head-major, rope'd, pre-scaled
__device__ __half g_k16[NH * SEQ * HD];     // head-major, rope'd
__device__ __half g_v16[NH * SEQ * HD];     // head-major

// ---------------------------------------------------------------------------
// helpers
// ---------------------------------------------------------------------------
__device__ __forceinline__ uint32_t h2_as_u32(__half2 h) {
    union { __half2 h2; uint32_t u; } cvt;
    cvt.h2 = h;
    return cvt.u;
}

__device__ __forceinline__ void mma_f16(float* d, const uint32_t* a, const uint32_t* b) {
    asm volatile(
        "mma.sync.aligned.m16n8k16.row.col.f32.f16.f16.f32 "
        "{%0,%1,%2,%3},{%4,%5,%6,%7},{%8,%9},{%0,%1,%2,%3};"
        : "+f"(d[0]), "+f"(d[1]), "+f"(d[2]), "+f"(d[3])
        : "r"(a[0]), "r"(a[1]), "r"(a[2]), "r"(a[3]),
          "r"(b[0]), "r"(b[1]));
}

__device__ __forceinline__ void ldsm_x4(uint32_t* r, uint32_t addr) {
    asm volatile("ldmatrix.sync.aligned.m8n8.x4.shared.b16 {%0,%1,%2,%3},[%4];"
        : "=r"(r[0]), "=r"(r[1]), "=r"(r[2]), "=r"(r[3]) : "r"(addr));
}

__device__ __forceinline__ void ldsm_x4_t(uint32_t* r, uint32_t addr) {
    asm volatile("ldmatrix.sync.aligned.m8n8.x4.trans.shared.b16 {%0,%1,%2,%3},[%4];"
        : "=r"(r[0]), "=r"(r[1]), "=r"(r[2]), "=r"(r[3]) : "r"(addr));
}

__device__ __forceinline__ void cp16(uint32_t dst, const void* src) {
    asm volatile("cp.async.ca.shared.global [%0], [%1], 16;" :: "r"(dst), "l"(src));
}
__device__ __forceinline__ void cp_commit() {
    asm volatile("cp.async.commit_group;");
}
__device__ __forceinline__ void cp_wait1() {
    asm volatile("cp.async.wait_group 1;");
}
__device__ __forceinline__ void cp_wait0() {
    asm volatile("cp.async.wait_group 0;");
}

// ---------------------------------------------------------------------------
// fp32 -> fp16 convert, 8 elems / thread
// ---------------------------------------------------------------------------
__global__ __launch_bounds__(256) void cvt_f2h(const float* __restrict__ src,
                                               __half* __restrict__ dst, int n8)
{
    int idx = blockIdx.x * blockDim.x + threadIdx.x;
    if (idx >= n8) return;
    float4 v0 = *reinterpret_cast<const float4*>(&src[idx * 8]);
    float4 v1 = *reinterpret_cast<const float4*>(&src[idx * 8 + 4]);
    __half2 h[4];
    h[0] = __floats2half2_rn(v0.x, v0.y);
    h[1] = __floats2half2_rn(v0.z, v0.w);
    h[2] = __floats2half2_rn(v1.x, v1.y);
    h[3] = __floats2half2_rn(v1.z, v1.w);
    *reinterpret_cast<uint4*>(&dst[idx * 8]) = *reinterpret_cast<uint4*>(h);
}

// ---------------------------------------------------------------------------
// HGEMM: C[M,N](fp32) = A[M,K](fp16) @ B[K,N](fp16) + bias[N](fp32)
// BM=128 BN=128 BK=32, 256 threads = 8 warps (2m x 4n), warp tile m64 x n32.
// Double-buffered cp.async.
// ---------------------------------------------------------------------------
#define GLDA 40    // A smem halves/row  (20 words, conflict-free under ldmatrix)
#define GLDB 136   // B smem halves/row  (68 words, conflict-free under ldmatrix)
#define A_STG (128 * GLDA)   // halves per stage
#define B_STG (32 * GLDB)

__global__ __launch_bounds__(256) void hgemm_bias(
    const __half* __restrict__ A, const __half* __restrict__ B,
    const float* __restrict__ bias, float* __restrict__ C,
    int M, int N, int K)
{
    __shared__ __half sA[2 * A_STG];
    __shared__ __half sB[2 * B_STG];

    const int tid  = threadIdx.x;
    const int wid  = tid >> 5;
    const int lane = tid & 31;
    const int wm   = wid >> 2;       // 0..1
    const int wn   = wid & 3;        // 0..3
    const int gid  = lane >> 2;
    const int tig  = lane & 3;
    const int j8   = lane & 7;
    const int grp  = lane >> 3;

    const int m0 = blockIdx.y * 128;
    const int n0 = blockIdx.x * 128;

    const uint32_t saBase = (uint32_t)__cvta_generic_to_shared(sA);
    const uint32_t sbBase = (uint32_t)__cvta_generic_to_shared(sB);

    // ldmatrix per-lane offsets (halves)
    const int aLane = ((grp & 1) * 8 + j8) * GLDA + (grp >> 1) * 8;  // A non-trans
    const int bLane = ((grp & 1) * 8 + j8) * GLDB + (grp >> 1) * 8;  // B trans

    // loader coords
    const int a_r = tid >> 1;            // uint4 pair: rows (2 uint4 per thread)
    const int a_q = tid & 1;             // base quad; threads cover 512 uint4 via 2 steps
    const int b_r = tid >> 4;
    const int b_q = tid & 15;

    float acc[4][4][4];
    #pragma unroll
    for (int i = 0; i < 4; i++)
        #pragma unroll
        for (int j = 0; j < 4; j++)
            #pragma unroll
            for (int c = 0; c < 4; c++) acc[i][j][c] = 0.f;

    const int NIT = K >> 5;

    // tile loader (cp.async): A 128x32, B 32x128
    auto load_tiles = [&](int stage, int k0) {
        // A: 512 uint4; thread does idx = tid and tid+256
        #pragma unroll
        for (int s = 0; s < 2; s++) {
            int idx = tid + s * 256;
            int r = idx >> 2, q = idx & 3;
            uint32_t dst = saBase + (uint32_t)(stage * A_STG + r * GLDA + q * 8) * 2u;
            cp16(dst, &A[(m0 + r) * K + k0 + q * 8]);
        }
        // B: 512 uint4
        #pragma unroll
        for (int s = 0; s < 2; s++) {
            int idx = tid + s * 256;
            int r = idx >> 4, q = idx & 15;
            uint32_t dst = sbBase + (uint32_t)(stage * B_STG + r * GLDB + q * 8) * 2u;
            cp16(dst, &B[(k0 + r) * N + n0 + q * 8]);
        }
    };

    load_tiles(0, 0);
    cp_commit();

    for (int it = 0; it < NIT; it++) {
        if (it + 1 < NIT) {
            load_tiles((it + 1) & 1, (it + 1) << 5);
            cp_commit();
            cp_wait1();
        } else {
            cp_wait0();
        }
        __syncthreads();

        const int stage = it & 1;
        const uint32_t aTile = saBase + (uint32_t)(stage * A_STG) * 2u;
        const uint32_t bTile = sbBase + (uint32_t)(stage * B_STG) * 2u;

        #pragma unroll
        for (int kk = 0; kk < 32; kk += 16) {
            uint32_t a[4][4];
            #pragma unroll
            for (int i = 0; i < 4; i++)
                ldsm_x4(a[i], aTile + (uint32_t)((wm * 64 + i * 16) * GLDA + kk + aLane) * 2u);
            uint32_t b4[2][4];
            #pragma unroll
            for (int jn = 0; jn < 2; jn++)
                ldsm_x4_t(b4[jn], bTile + (uint32_t)(kk * GLDB + wn * 32 + jn * 16 + bLane) * 2u);
            #pragma unroll
            for (int i = 0; i < 4; i++) {
                mma_f16(acc[i][0], a[i], b4[0]);
                mma_f16(acc[i][1], a[i], b4[0] + 2);
                mma_f16(acc[i][2], a[i], b4[1]);
                mma_f16(acc[i][3], a[i], b4[1] + 2);
            }
        }
        __syncthreads();
    }

    // epilogue
    #pragma unroll
    for (int i = 0; i < 4; i++) {
        int r0 = m0 + wm * 64 + i * 16 + gid;
        #pragma unroll
        for (int j = 0; j < 4; j++) {
            int col = n0 + wn * 32 + j * 8 + 2 * tig;
            float bx = bias[col], by = bias[col + 1];
            float2 v0 = make_float2(acc[i][j][0] + bx, acc[i][j][1] + by);
            float2 v1 = make_float2(acc[i][j][2] + bx, acc[i][j][3] + by);
            *reinterpret_cast<float2*>(&C[r0 * N + col])       = v0;
            *reinterpret_cast<float2*>(&C[(r0 + 8) * N + col]) = v1;
        }
    }
}

// ---------------------------------------------------------------------------
// RoPE + fp16 convert for Q and K (head-major output). Q pre-scaled.
// ---------------------------------------------------------------------------
__global__ __launch_bounds__(256) void rope_cvt(const float* __restrict__ qkv,
                                                const int* __restrict__ pos)
{
    const int total = SEQ * 2 * NH * RD;
    int idx = blockIdx.x * blockDim.x + threadIdx.x;
    if (idx >= total) return;

    int d = idx % RD;
    int h = (idx / RD) % NH;
    int s = (idx / (RD * NH)) & 1;     // 0 = q, 1 = k
    int t = idx / (RD * NH * 2);

    int i = (d < 20) ? d : (d - 20);
    float p = (float)pos[t * 2 + ((d < 20) ? 0 : 1)];
    float ang = p * exp2f(-0.66438561897747246f * (float)i);
    float sv, cv;
    sincosf(ang, &sv, &cv);

    const float* src = &qkv[t * QKV_N + s * HIDDEN + h * HD];
    float x0 = src[d];
    float x1 = src[d + RD];
    float y0 = x0 * cv - x1 * sv;
    float y1 = x1 * cv + x0 * sv;

    float sc = s ? 1.0f : 0.11180339887498949f;   // q pre-scaled by 80^-0.5
    __half* dst = s ? g_k16 : g_q16;
    dst[(h * SEQ + t) * HD + d]      = __float2half(y0 * sc);
    dst[(h * SEQ + t) * HD + d + RD] = __float2half(y1 * sc);
}

// ---------------------------------------------------------------------------
// V fp16 convert (head-major).
// ---------------------------------------------------------------------------
__global__ __launch_bounds__(256) void v_cvt(const float* __restrict__ qkv)
{
    const int total = SEQ * NH * (HD / 4);
    int idx = blockIdx.x * blockDim.x + threadIdx.x;
    if (idx >= total) return;
    int c4 = idx % (HD / 4);
    int h  = (idx / (HD / 4)) % NH;
    int t  = idx / ((HD / 4) * NH);

    float4 v = *reinterpret_cast<const float4*>(
        &qkv[t * QKV_N + 2 * HIDDEN + h * HD + c4 * 4]);
    __half2* dst = reinterpret_cast<__half2*>(&g_v16[(h * SEQ + t) * HD + c4 * 4]);
    dst[0] = __floats2half2_rn(v.x, v.y);
    dst[1] = __floats2half2_rn(v.z, v.w);
}

// ---------------------------------------------------------------------------
// Flash attention, fp16 mma m16n8k16, P in registers. Output fp16.
// ---------------------------------------------------------------------------
#define LDH 88

__global__ __launch_bounds__(128, 4) void attn_kernel()
{
    __shared__ __half sK[64 * LDH];
    __shared__ __half sV[64 * LDH];

    const int h   = blockIdx.y;
    const int q0  = blockIdx.x * 64;
    const int tid = threadIdx.x;
    const int w    = tid >> 5;
    const int lane = tid & 31;
    const int gid  = lane >> 2;
    const int tig  = lane & 3;
    const int j8   = lane & 7;
    const int grp  = lane >> 3;

    const uint32_t skBase = (uint32_t)__cvta_generic_to_shared(sK);
    const uint32_t svBase = (uint32_t)__cvta_generic_to_shared(sV);
    const int kOff = ((grp >> 1) * 8 + j8) * LDH + (grp & 1) * 8;
    const int vOff = ((grp & 1) * 8 + j8) * LDH + (grp >> 1) * 8;

    {
        const __half* qg = &g_q16[(h * SEQ + q0) * HD];
        #pragma unroll
        for (int i = tid; i < 640; i += 128) {
            int r = i / 10, c = i % 10;
            *reinterpret_cast<uint4*>(&sK[r * LDH + c * 8]) =
                *reinterpret_cast<const uint4*>(&qg[r * HD + c * 8]);
        }
    }
    __syncthreads();

    uint32_t qa[5][4];
    const int qrow = 16 * w + gid;
    #pragma unroll
    for (int t = 0; t < 5; t++) {
        qa[t][0] = *reinterpret_cast<uint32_t*>(&sK[ qrow      * LDH + t * 16 + 2 * tig]);
        qa[t][1] = *reinterpret_cast<uint32_t*>(&sK[(qrow + 8) * LDH + t * 16 + 2 * tig]);
        qa[t][2] = *reinterpret_cast<uint32_t*>(&sK[ qrow      * LDH + t * 16 + 2 * tig + 8]);
        qa[t][3] = *reinterpret_cast<uint32_t*>(&sK[(qrow + 8) * LDH + t * 16 + 2 * tig + 8]);
    }

    float m0r = -1e30f, m1r = -1e30f, l0 = 0.f, l1 = 0.f;
    float acc[10][4];
    #pragma unroll
    for (int n = 0; n < 10; n++)
        #pragma unroll
        for (int jj = 0; jj < 4; jj++) acc[n][jj] = 0.f;

    for (int kt = 0; kt < SEQ / 64; kt++) {
        const int k0 = kt * 64;
        __syncthreads();

        {
            const __half* kg = &g_k16[(h * SEQ + k0) * HD];
            const __half* vg = &g_v16[(h * SEQ + k0) * HD];
            #pragma unroll
            for (int i = tid; i < 640; i += 128) {
                int r = i / 10, c = i % 10;
                *reinterpret_cast<uint4*>(&sK[r * LDH + c * 8]) =
                    *reinterpret_cast<const uint4*>(&kg[r * HD + c * 8]);
                *reinterpret_cast<uint4*>(&sV[r * LDH + c * 8]) =
                    *reinterpret_cast<const uint4*>(&vg[r * HD + c * 8]);
            }
        }
        __syncthreads();

        float sf[8][4];
        #pragma unroll
        for (int n = 0; n < 8; n++)
            #pragma unroll
            for (int jj = 0; jj < 4; jj++) sf[n][jj] = 0.f;

        #pragma unroll
        for (int t = 0; t < 5; t++) {
            #pragma unroll
            for (int np = 0; np < 4; np++) {
                uint32_t b[4];
                ldsm_x4(b, skBase + (uint32_t)(np * 16 * LDH + t * 16 + kOff) * 2u);
                mma_f16(sf[2 * np],     qa[t], b);
                mma_f16(sf[2 * np + 1], qa[t], b + 2);
            }
        }

        float mx0 = -1e30f, mx1 = -1e30f;
        #pragma unroll
        for (int n = 0; n < 8; n++) {
            mx0 = fmaxf(mx0, fmaxf(sf[n][0], sf[n][1]));
            mx1 = fmaxf(mx1, fmaxf(sf[n][2], sf[n][3]));
        }
        #pragma unroll
        for (int o = 1; o <= 2; o <<= 1) {
            mx0 = fmaxf(mx0, __shfl_xor_sync(0xffffffffu, mx0, o));
            mx1 = fmaxf(mx1, __shfl_xor_sync(0xffffffffu, mx1, o));
        }
        float nm0 = fmaxf(m0r, mx0), nm1 = fmaxf(m1r, mx1);
        float c0 = __expf(m0r - nm0), c1 = __expf(m1r - nm1);
        m0r = nm0; m1r = nm1;

        float s0 = 0.f, s1 = 0.f;
        #pragma unroll
        for (int n = 0; n < 8; n++) {
            sf[n][0] = __expf(sf[n][0] - nm0);
            sf[n][1] = __expf(sf[n][1] - nm0);
            sf[n][2] = __expf(sf[n][2] - nm1);
            sf[n][3] = __expf(sf[n][3] - nm1);
            s0 += sf[n][0] + sf[n][1];
            s1 += sf[n][2] + sf[n][3];
        }
        #pragma unroll
        for (int o = 1; o <= 2; o <<= 1) {
            s0 += __shfl_xor_sync(0xffffffffu, s0, o);
            s1 += __shfl_xor_sync(0xffffffffu, s1, o);
        }
        l0 = l0 * c0 + s0;
        l1 = l1 * c1 + s1;
        #pragma unroll
        for (int n = 0; n < 10; n++) {
            acc[n][0] *= c0; acc[n][1] *= c0;
            acc[n][2] *= c1; acc[n][3] *= c1;
        }

        #pragma unroll
        for (int s = 0; s < 4; s++) {
            uint32_t pa[4];
            pa[0] = h2_as_u32(__floats2half2_rn(sf[2*s][0],   sf[2*s][1]));
            pa[1] = h2_as_u32(__floats2half2_rn(sf[2*s][2],   sf[2*s][3]));
            pa[2] = h2_as_u32(__floats2half2_rn(sf[2*s+1][0], sf[2*s+1][1]));
            pa[3] = h2_as_u32(__floats2half2_rn(sf[2*s+1][2], sf[2*s+1][3]));
            #pragma unroll
            for (int np = 0; np < 5; np++) {
                uint32_t b[4];
                ldsm_x4_t(b, svBase + (uint32_t)(s * 16 * LDH + np * 16 + vOff) * 2u);
                mma_f16(acc[2 * np],     pa, b);
                mma_f16(acc[2 * np + 1], pa, b + 2);
            }
        }
    }

    // epilogue: normalize, store fp16
    float i0 = 1.0f / l0, i1 = 1.0f / l1;
    #pragma unroll
    for (int n = 0; n < 10; n++) {
        int col = h * HD + n * 8 + 2 * tig;
        __half2 v0 = __floats2half2_rn(acc[n][0] * i0, acc[n][1] * i0);
        __half2 v1 = __floats2half2_rn(acc[n][2] * i1, acc[n][3] * i1);
        *reinterpret_cast<__half2*>(&g_att16[(q0 + qrow)     * HIDDEN + col]) = v0;
        *reinterpret_cast<__half2*>(&g_att16[(q0 + qrow + 8) * HIDDEN + col]) = v1;
    }
}

// ---------------------------------------------------------------------------
extern "C" void kernel_launch(void* const* d_in, const int* in_sizes, int n_in,
                              void* d_out, int out_size)
{
    const float* hs    = (const float*)d_in[0];
    const int*   pos   = (const int*)d_in[1];
    const float* qkv_w = (const float*)d_in[2];
    const float* qkv_b = (const float*)d_in[3];
    const float* o_w   = (const float*)d_in[4];
    const float* o_b   = (const float*)d_in[5];
    float* out = (float*)d_out;

    float*  qkv_ptr = nullptr;
    __half* hs16    = nullptr;
    __half* qw16    = nullptr;
    __half* ow16    = nullptr;
    __half* att16   = nullptr;
    cudaGetSymbolAddress((void**)&qkv_ptr, g_qkv);
    cudaGetSymbolAddress((void**)&hs16,    g_hs16);
    cudaGetSymbolAddress((void**)&qw16,    g_qw16);
    cudaGetSymbolAddress((void**)&ow16,    g_ow16);
    cudaGetSymbolAddress((void**)&att16,   g_att16);

    // 0) fp32 -> fp16 conversions
    {
        int n8 = SEQ * HIDDEN / 8;
        cvt_f2h<<<(n8 + 255) / 256, 256>>>(hs, hs16, n8);
        n8 = HIDDEN * QKV_N / 8;
        cvt_f2h<<<(n8 + 255) / 256, 256>>>(qkv_w, qw16, n8);
        n8 = HIDDEN * HIDDEN / 8;
        cvt_f2h<<<(n8 + 255) / 256, 256>>>(o_w, ow16, n8);
    }
    // 1) QKV GEMM + bias (fp16 tensor cores, fp32 out)
    {
        dim3 grid(QKV_N / 128, SEQ / 128);  // (30, 24)
        hgemm_bias<<<grid, 256>>>(hs16, qw16, qkv_b, qkv_ptr, SEQ, QKV_N, HIDDEN);
    }
    // 2) RoPE + fp16 convert (q,k), fp16 convert (v)
    {
        int total = SEQ * 2 * NH * RD;
        rope_cvt<<<(total + 255) / 256, 256>>>(qkv_ptr, pos);
        int totv = SEQ * NH * (HD / 4);
        v_cvt<<<(totv + 255) / 256, 256>>>(qkv_ptr);
    }
    // 3) Attention (fp16 tensor cores, register-resident P, fp16 out)
    {
        dim3 grid(SEQ / 64, NH);
        attn_kernel<<<grid, 128>>>();
    }
    // 4) O GEMM + bias (fp16 tensor cores, fp32 out)
    {
        dim3 grid(HIDDEN / 128, SEQ / 128);  // (10, 24)
        hgemm_bias<<<grid, 256>>>(att16, ow16, o_b, out, SEQ, HIDDEN, HIDDEN);
    }
}

// round 6
// speedup vs baseline: 7.5157x; 1.0164x over previous
#include <cuda_runtime.h>
#include <cuda_fp16.h>
#include <math.h>
#include <stdint.h>

#define SEQ 3072
#define HIDDEN 1280
#define NH 16
#define HD 80
#define RD 40
#define QKV_N (3 * HIDDEN)

// Scratch (allocation-free rule: __device__ globals)
__device__ float  g_qkv[SEQ * QKV_N];       // QKV GEMM output (fp32)
__device__ __half g_hs16[SEQ * HIDDEN];     // hidden_states fp16
__device__ __half g_qw16[HIDDEN * QKV_N];   // qkv_w fp16
__device__ __half g_ow16[HIDDEN * HIDDEN];  // o_w fp16
__device__ __half g_att16[SEQ * HIDDEN];    // attention output fp16
__device__ __half g_q16[NH * SEQ * HD];     // head-major, rope'd, pre-scaled
__device__ __half g_k16[NH * SEQ * HD];     // head-major, rope'd
__device__ __half g_v16[NH * SEQ * HD];     // head-major

// ---------------------------------------------------------------------------
// helpers
// ---------------------------------------------------------------------------
__device__ __forceinline__ uint32_t h2_as_u32(__half2 h) {
    union { __half2 h2; uint32_t u; } cvt;
    cvt.h2 = h;
    return cvt.u;
}

__device__ __forceinline__ void mma_f16(float* d, const uint32_t* a, const uint32_t* b) {
    asm volatile(
        "mma.sync.aligned.m16n8k16.row.col.f32.f16.f16.f32 "
        "{%0,%1,%2,%3},{%4,%5,%6,%7},{%8,%9},{%0,%1,%2,%3};"
        : "+f"(d[0]), "+f"(d[1]), "+f"(d[2]), "+f"(d[3])
        : "r"(a[0]), "r"(a[1]), "r"(a[2]), "r"(a[3]),
          "r"(b[0]), "r"(b[1]));
}

__device__ __forceinline__ void ldsm_x4(uint32_t* r, uint32_t addr) {
    asm volatile("ldmatrix.sync.aligned.m8n8.x4.shared.b16 {%0,%1,%2,%3},[%4];"
        : "=r"(r[0]), "=r"(r[1]), "=r"(r[2]), "=r"(r[3]) : "r"(addr));
}

__device__ __forceinline__ void ldsm_x4_t(uint32_t* r, uint32_t addr) {
    asm volatile("ldmatrix.sync.aligned.m8n8.x4.trans.shared.b16 {%0,%1,%2,%3},[%4];"
        : "=r"(r[0]), "=r"(r[1]), "=r"(r[2]), "=r"(r[3]) : "r"(addr));
}

__device__ __forceinline__ void cp16(uint32_t dst, const void* src) {
    asm volatile("cp.async.ca.shared.global [%0], [%1], 16;" :: "r"(dst), "l"(src));
}
__device__ __forceinline__ void cp_commit() { asm volatile("cp.async.commit_group;"); }
__device__ __forceinline__ void cp_wait0() { asm volatile("cp.async.wait_group 0;"); }
__device__ __forceinline__ void cp_wait1() { asm volatile("cp.async.wait_group 1;"); }
__device__ __forceinline__ void cp_wait2() { asm volatile("cp.async.wait_group 2;"); }
__device__ __forceinline__ void cp_wait3() { asm volatile("cp.async.wait_group 3;"); }

// ---------------------------------------------------------------------------
// fp32 -> fp16 convert, 8 elems / thread
// ---------------------------------------------------------------------------
__global__ __launch_bounds__(256) void cvt_f2h(const float* __restrict__ src,
                                               __half* __restrict__ dst, int n8)
{
    int idx = blockIdx.x * blockDim.x + threadIdx.x;
    if (idx >= n8) return;
    float4 v0 = *reinterpret_cast<const float4*>(&src[idx * 8]);
    float4 v1 = *reinterpret_cast<const float4*>(&src[idx * 8 + 4]);
    __half2 h[4];
    h[0] = __floats2half2_rn(v0.x, v0.y);
    h[1] = __floats2half2_rn(v0.z, v0.w);
    h[2] = __floats2half2_rn(v1.x, v1.y);
    h[3] = __floats2half2_rn(v1.z, v1.w);
    *reinterpret_cast<uint4*>(&dst[idx * 8]) = *reinterpret_cast<uint4*>(h);
}

// ---------------------------------------------------------------------------
// HGEMM: C[M,N](fp32) = A[M,K](fp16) @ B[K,N](fp16) + bias[N](fp32)
// BM=128 BN=128 BK=32, 256 threads = 8 warps (2m x 4n), warp tile m64 x n32.
// 4-stage cp.async ring (dynamic smem 75776 B).
// ---------------------------------------------------------------------------
#define GLDA 40
#define GLDB 136
#define A_STG (128 * GLDA)
#define B_STG (32 * GLDB)
#define NSTG 4
#define HG_SMEM ((NSTG * (A_STG + B_STG)) * 2)

__global__ __launch_bounds__(256) void hgemm_bias(
    const __half* __restrict__ A, const __half* __restrict__ B,
    const float* __restrict__ bias, float* __restrict__ C,
    int M, int N, int K)
{
    extern __shared__ __half hsm[];
    __half* sA = hsm;
    __half* sB = hsm + NSTG * A_STG;

    const int tid  = threadIdx.x;
    const int wid  = tid >> 5;
    const int lane = tid & 31;
    const int wm   = wid >> 2;
    const int wn   = wid & 3;
    const int gid  = lane >> 2;
    const int tig  = lane & 3;
    const int j8   = lane & 7;
    const int grp  = lane >> 3;

    const int m0 = blockIdx.y * 128;
    const int n0 = blockIdx.x * 128;

    const uint32_t saBase = (uint32_t)__cvta_generic_to_shared(sA);
    const uint32_t sbBase = (uint32_t)__cvta_generic_to_shared(sB);

    const int aLane = ((grp & 1) * 8 + j8) * GLDA + (grp >> 1) * 8;
    const int bLane = ((grp & 1) * 8 + j8) * GLDB + (grp >> 1) * 8;

    float acc[4][4][4];
    #pragma unroll
    for (int i = 0; i < 4; i++)
        #pragma unroll
        for (int j = 0; j < 4; j++)
            #pragma unroll
            for (int c = 0; c < 4; c++) acc[i][j][c] = 0.f;

    const int NIT = K >> 5;   // 40 for these shapes (>= NSTG-1 prologue loads)

    auto load_tiles = [&](int stage, int k0) {
        #pragma unroll
        for (int s = 0; s < 2; s++) {
            int idx = tid + s * 256;
            int r = idx >> 2, q = idx & 3;
            uint32_t dst = saBase + (uint32_t)(stage * A_STG + r * GLDA + q * 8) * 2u;
            cp16(dst, &A[(m0 + r) * K + k0 + q * 8]);
        }
        #pragma unroll
        for (int s = 0; s < 2; s++) {
            int idx = tid + s * 256;
            int r = idx >> 4, q = idx & 15;
            uint32_t dst = sbBase + (uint32_t)(stage * B_STG + r * GLDB + q * 8) * 2u;
            cp16(dst, &B[(k0 + r) * N + n0 + q * 8]);
        }
    };

    load_tiles(0, 0);  cp_commit();
    load_tiles(1, 32); cp_commit();
    load_tiles(2, 64); cp_commit();

    for (int it = 0; it < NIT; it++) {
        if (it + 3 < NIT) {
            load_tiles((it + 3) & 3, (it + 3) << 5);
            cp_commit();
        }
        int rem = NIT - 1 - it;
        if (rem >= 3)      cp_wait3();
        else if (rem == 2) cp_wait2();
        else if (rem == 1) cp_wait1();
        else               cp_wait0();
        __syncthreads();

        const int stage = it & 3;
        const uint32_t aTile = saBase + (uint32_t)(stage * A_STG) * 2u;
        const uint32_t bTile = sbBase + (uint32_t)(stage * B_STG) * 2u;

        #pragma unroll
        for (int kk = 0; kk < 32; kk += 16) {
            uint32_t a[4][4];
            #pragma unroll
            for (int i = 0; i < 4; i++)
                ldsm_x4(a[i], aTile + (uint32_t)((wm * 64 + i * 16) * GLDA + kk + aLane) * 2u);
            uint32_t b4[2][4];
            #pragma unroll
            for (int jn = 0; jn < 2; jn++)
                ldsm_x4_t(b4[jn], bTile + (uint32_t)(kk * GLDB + wn * 32 + jn * 16 + bLane) * 2u);
            #pragma unroll
            for (int i = 0; i < 4; i++) {
                mma_f16(acc[i][0], a[i], b4[0]);
                mma_f16(acc[i][1], a[i], b4[0] + 2);
                mma_f16(acc[i][2], a[i], b4[1]);
                mma_f16(acc[i][3], a[i], b4[1] + 2);
            }
        }
        __syncthreads();
    }

    #pragma unroll
    for (int i = 0; i < 4; i++) {
        int r0 = m0 + wm * 64 + i * 16 + gid;
        #pragma unroll
        for (int j = 0; j < 4; j++) {
            int col = n0 + wn * 32 + j * 8 + 2 * tig;
            float bx = bias[col], by = bias[col + 1];
            float2 v0 = make_float2(acc[i][j][0] + bx, acc[i][j][1] + by);
            float2 v1 = make_float2(acc[i][j][2] + bx, acc[i][j][3] + by);
            *reinterpret_cast<float2*>(&C[r0 * N + col])       = v0;
            *reinterpret_cast<float2*>(&C[(r0 + 8) * N + col]) = v1;
        }
    }
}

// ---------------------------------------------------------------------------
// RoPE + fp16 convert for Q and K (head-major output). Q pre-scaled.
// ---------------------------------------------------------------------------
__global__ __launch_bounds__(256) void rope_cvt(const float* __restrict__ qkv,
                                                const int* __restrict__ pos)
{
    const int total = SEQ * 2 * NH * RD;
    int idx = blockIdx.x * blockDim.x + threadIdx.x;
    if (idx >= total) return;

    int d = idx % RD;
    int h = (idx / RD) % NH;
    int s = (idx / (RD * NH)) & 1;     // 0 = q, 1 = k
    int t = idx / (RD * NH * 2);

    int i = (d < 20) ? d : (d - 20);
    float p = (float)pos[t * 2 + ((d < 20) ? 0 : 1)];
    float ang = p * exp2f(-0.66438561897747246f * (float)i);
    float sv, cv;
    sincosf(ang, &sv, &cv);

    const float* src = &qkv[t * QKV_N + s * HIDDEN + h * HD];
    float x0 = src[d];
    float x1 = src[d + RD];
    float y0 = x0 * cv - x1 * sv;
    float y1 = x1 * cv + x0 * sv;

    float sc = s ? 1.0f : 0.11180339887498949f;   // q pre-scaled by 80^-0.5
    __half* dst = s ? g_k16 : g_q16;
    dst[(h * SEQ + t) * HD + d]      = __float2half(y0 * sc);
    dst[(h * SEQ + t) * HD + d + RD] = __float2half(y1 * sc);
}

// ---------------------------------------------------------------------------
// V fp16 convert (head-major).
// ---------------------------------------------------------------------------
__global__ __launch_bounds__(256) void v_cvt(const float* __restrict__ qkv)
{
    const int total = SEQ * NH * (HD / 4);
    int idx = blockIdx.x * blockDim.x + threadIdx.x;
    if (idx >= total) return;
    int c4 = idx % (HD / 4);
    int h  = (idx / (HD / 4)) % NH;
    int t  = idx / ((HD / 4) * NH);

    float4 v = *reinterpret_cast<const float4*>(
        &qkv[t * QKV_N + 2 * HIDDEN + h * HD + c4 * 4]);
    __half2* dst = reinterpret_cast<__half2*>(&g_v16[(h * SEQ + t) * HD + c4 * 4]);
    dst[0] = __floats2half2_rn(v.x, v.y);
    dst[1] = __floats2half2_rn(v.z, v.w);
}

// ---------------------------------------------------------------------------
// Flash attention, fp16 mma m16n8k16, P in registers, 2-stage cp.async K/V.
// Grid (SEQ/64, NH), 128 threads. smem: 2 stages x (sK + sV) 64x88 halves.
// ---------------------------------------------------------------------------
#define LDH 88
#define KV_STG (64 * LDH)   // halves per stage per tensor

__global__ __launch_bounds__(128, 4) void attn_kernel()
{
    __shared__ __half sK[2 * KV_STG];
    __shared__ __half sV[2 * KV_STG];

    const int h   = blockIdx.y;
    const int q0  = blockIdx.x * 64;
    const int tid = threadIdx.x;
    const int w    = tid >> 5;
    const int lane = tid & 31;
    const int gid  = lane >> 2;
    const int tig  = lane & 3;
    const int j8   = lane & 7;
    const int grp  = lane >> 3;

    const uint32_t skBase = (uint32_t)__cvta_generic_to_shared(sK);
    const uint32_t svBase = (uint32_t)__cvta_generic_to_shared(sV);
    const int kOff = ((grp >> 1) * 8 + j8) * LDH + (grp & 1) * 8;
    const int vOff = ((grp & 1) * 8 + j8) * LDH + (grp >> 1) * 8;

    // ---- Stage Q via sK stage 0, extract register fragments ----
    {
        const __half* qg = &g_q16[(h * SEQ + q0) * HD];
        #pragma unroll
        for (int i = tid; i < 640; i += 128) {
            int r = i / 10, c = i % 10;
            *reinterpret_cast<uint4*>(&sK[r * LDH + c * 8]) =
                *reinterpret_cast<const uint4*>(&qg[r * HD + c * 8]);
        }
    }
    __syncthreads();

    uint32_t qa[5][4];
    const int qrow = 16 * w + gid;
    #pragma unroll
    for (int t = 0; t < 5; t++) {
        qa[t][0] = *reinterpret_cast<uint32_t*>(&sK[ qrow      * LDH + t * 16 + 2 * tig]);
        qa[t][1] = *reinterpret_cast<uint32_t*>(&sK[(qrow + 8) * LDH + t * 16 + 2 * tig]);
        qa[t][2] = *reinterpret_cast<uint32_t*>(&sK[ qrow      * LDH + t * 16 + 2 * tig + 8]);
        qa[t][3] = *reinterpret_cast<uint32_t*>(&sK[(qrow + 8) * LDH + t * 16 + 2 * tig + 8]);
    }
    __syncthreads();   // Q extraction done; sK stage 0 free for K tile 0

    // loader coords (fixed per thread): 640 uint4 per tensor per tile
    const int lr0 = tid >> 1;            // reuse pattern: idx = tid + s*128
    (void)lr0;

    auto load_kv = [&](int stage, int k0) {
        const __half* kg = &g_k16[(h * SEQ + k0) * HD];
        const __half* vg = &g_v16[(h * SEQ + k0) * HD];
        #pragma unroll
        for (int s = 0; s < 5; s++) {
            int idx = tid + s * 128;
            int r = idx / 10, c = idx % 10;
            uint32_t off = (uint32_t)(stage * KV_STG + r * LDH + c * 8) * 2u;
            cp16(skBase + off, &kg[r * HD + c * 8]);
            cp16(svBase + off, &vg[r * HD + c * 8]);
        }
    };

    load_kv(0, 0);
    cp_commit();

    float m0r = -1e30f, m1r = -1e30f, l0 = 0.f, l1 = 0.f;
    float acc[10][4];
    #pragma unroll
    for (int n = 0; n < 10; n++)
        #pragma unroll
        for (int jj = 0; jj < 4; jj++) acc[n][jj] = 0.f;

    const int NT = SEQ / 64;
    for (int kt = 0; kt < NT; kt++) {
        if (kt + 1 < NT) {
            load_kv((kt + 1) & 1, (kt + 1) * 64);
            cp_commit();
            cp_wait1();
        } else {
            cp_wait0();
        }
        __syncthreads();   // tile kt ready; all warps past reads of the other stage

        const uint32_t kTile = skBase + (uint32_t)((kt & 1) * KV_STG) * 2u;
        const uint32_t vTile = svBase + (uint32_t)((kt & 1) * KV_STG) * 2u;

        // ---- S = Q @ K^T ----
        float sf[8][4];
        #pragma unroll
        for (int n = 0; n < 8; n++)
            #pragma unroll
            for (int jj = 0; jj < 4; jj++) sf[n][jj] = 0.f;

        #pragma unroll
        for (int t = 0; t < 5; t++) {
            #pragma unroll
            for (int np = 0; np < 4; np++) {
                uint32_t b[4];
                ldsm_x4(b, kTile + (uint32_t)(np * 16 * LDH + t * 16 + kOff) * 2u);
                mma_f16(sf[2 * np],     qa[t], b);
                mma_f16(sf[2 * np + 1], qa[t], b + 2);
            }
        }

        // ---- Online softmax ----
        float mx0 = -1e30f, mx1 = -1e30f;
        #pragma unroll
        for (int n = 0; n < 8; n++) {
            mx0 = fmaxf(mx0, fmaxf(sf[n][0], sf[n][1]));
            mx1 = fmaxf(mx1, fmaxf(sf[n][2], sf[n][3]));
        }
        #pragma unroll
        for (int o = 1; o <= 2; o <<= 1) {
            mx0 = fmaxf(mx0, __shfl_xor_sync(0xffffffffu, mx0, o));
            mx1 = fmaxf(mx1, __shfl_xor_sync(0xffffffffu, mx1, o));
        }
        float nm0 = fmaxf(m0r, mx0), nm1 = fmaxf(m1r, mx1);
        float c0 = __expf(m0r - nm0), c1 = __expf(m1r - nm1);
        m0r = nm0; m1r = nm1;

        float s0 = 0.f, s1 = 0.f;
        #pragma unroll
        for (int n = 0; n < 8; n++) {
            sf[n][0] = __expf(sf[n][0] - nm0);
            sf[n][1] = __expf(sf[n][1] - nm0);
            sf[n][2] = __expf(sf[n][2] - nm1);
            sf[n][3] = __expf(sf[n][3] - nm1);
            s0 += sf[n][0] + sf[n][1];
            s1 += sf[n][2] + sf[n][3];
        }
        #pragma unroll
        for (int o = 1; o <= 2; o <<= 1) {
            s0 += __shfl_xor_sync(0xffffffffu, s0, o);
            s1 += __shfl_xor_sync(0xffffffffu, s1, o);
        }
        l0 = l0 * c0 + s0;
        l1 = l1 * c1 + s1;
        #pragma unroll
        for (int n = 0; n < 10; n++) {
            acc[n][0] *= c0; acc[n][1] *= c0;
            acc[n][2] *= c1; acc[n][3] *= c1;
        }

        // ---- O += P @ V (register-resident P) ----
        #pragma unroll
        for (int s = 0; s < 4; s++) {
            uint32_t pa[4];
            pa[0] = h2_as_u32(__floats2half2_rn(sf[2*s][0],   sf[2*s][1]));
            pa[1] = h2_as_u32(__floats2half2_rn(sf[2*s][2],   sf[2*s][3]));
            pa[2] = h2_as_u32(__floats2half2_rn(sf[2*s+1][0], sf[2*s+1][1]));
            pa[3] = h2_as_u32(__floats2half2_rn(sf[2*s+1][2], sf[2*s+1][3]));
            #pragma unroll
            for (int np = 0; np < 5; np++) {
                uint32_t b[4];
                ldsm_x4_t(b, vTile + (uint32_t)(s * 16 * LDH + np * 16 + vOff) * 2u);
                mma_f16(acc[2 * np],     pa, b);
                mma_f16(acc[2 * np + 1], pa, b + 2);
            }
        }
        __syncthreads();   // done reading this stage before it is overwritten
    }

    // ---- Epilogue: normalize, store fp16 ----
    float i0 = 1.0f / l0, i1 = 1.0f / l1;
    #pragma unroll
    for (int n = 0; n < 10; n++) {
        int col = h * HD + n * 8 + 2 * tig;
        __half2 v0 = __floats2half2_rn(acc[n][0] * i0, acc[n][1] * i0);
        __half2 v1 = __floats2half2_rn(acc[n][2] * i1, acc[n][3] * i1);
        *reinterpret_cast<__half2*>(&g_att16[(q0 + qrow)     * HIDDEN + col]) = v0;
        *reinterpret_cast<__half2*>(&g_att16[(q0 + qrow + 8) * HIDDEN + col]) = v1;
    }
}

// ---------------------------------------------------------------------------
extern "C" void kernel_launch(void* const* d_in, const int* in_sizes, int n_in,
                              void* d_out, int out_size)
{
    const float* hs    = (const float*)d_in[0];
    const int*   pos   = (const int*)d_in[1];
    const float* qkv_w = (const float*)d_in[2];
    const float* qkv_b = (const float*)d_in[3];
    const float* o_w   = (const float*)d_in[4];
    const float* o_b   = (const float*)d_in[5];
    float* out = (float*)d_out;

    float*  qkv_ptr = nullptr;
    __half* hs16    = nullptr;
    __half* qw16    = nullptr;
    __half* ow16    = nullptr;
    __half* att16   = nullptr;
    cudaGetSymbolAddress((void**)&qkv_ptr, g_qkv);
    cudaGetSymbolAddress((void**)&hs16,    g_hs16);
    cudaGetSymbolAddress((void**)&qw16,    g_qw16);
    cudaGetSymbolAddress((void**)&ow16,    g_ow16);
    cudaGetSymbolAddress((void**)&att16,   g_att16);

    cudaFuncSetAttribute(hgemm_bias, cudaFuncAttributeMaxDynamicSharedMemorySize,
                         HG_SMEM);

    // 0) fp32 -> fp16 conversions
    {
        int n8 = SEQ * HIDDEN / 8;
        cvt_f2h<<<(n8 + 255) / 256, 256>>>(hs, hs16, n8);
        n8 = HIDDEN * QKV_N / 8;
        cvt_f2h<<<(n8 + 255) / 256, 256>>>(qkv_w, qw16, n8);
        n8 = HIDDEN * HIDDEN / 8;
        cvt_f2h<<<(n8 + 255) / 256, 256>>>(o_w, ow16, n8);
    }
    // 1) QKV GEMM + bias
    {
        dim3 grid(QKV_N / 128, SEQ / 128);  // (30, 24)
        hgemm_bias<<<grid, 256, HG_SMEM>>>(hs16, qw16, qkv_b, qkv_ptr, SEQ, QKV_N, HIDDEN);
    }
    // 2) RoPE + fp16 convert (q,k), fp16 convert (v)
    {
        int total = SEQ * 2 * NH * RD;
        rope_cvt<<<(total + 255) / 256, 256>>>(qkv_ptr, pos);
        int totv = SEQ * NH * (HD / 4);
        v_cvt<<<(totv + 255) / 256, 256>>>(qkv_ptr);
    }
    // 3) Attention (fp16 tensor cores, register P, cp.async pipeline)
    {
        dim3 grid(SEQ / 64, NH);
        attn_kernel<<<grid, 128>>>();
    }
    // 4) O GEMM + bias
    {
        dim3 grid(HIDDEN / 128, SEQ / 128);  // (10, 24)
        hgemm_bias<<<grid, 256, HG_SMEM>>>(att16, ow16, o_b, out, SEQ, HIDDEN, HIDDEN);
    }
}

// round 7
// speedup vs baseline: 7.8535x; 1.0449x over previous
#include <cuda_runtime.h>
#include <cuda_fp16.h>
#include <math.h>
#include <stdint.h>

#define SEQ 3072
#define HIDDEN 1280
#define NH 16
#define HD 80
#define RD 40
#define QKV_N (3 * HIDDEN)
#define KSPLIT 2

// Scratch (allocation-free rule: __device__ globals)
__device__ float  g_qkv[SEQ * QKV_N];       // QKV GEMM output (fp32)
__device__ __half g_hs16[SEQ * HIDDEN];     // hidden_states fp16
__device__ __half g_qw16[HIDDEN * QKV_N];   // qkv_w fp16
__device__ __half g_ow16[HIDDEN * HIDDEN];  // o_w fp16
__device__ __half g_att16[SEQ * HIDDEN];    // attention output fp16
__device__ __half g_q16[NH * SEQ * HD];     // head-major, rope'd, pre-scaled
__device__ __half g_k16[NH * SEQ * HD];     // head-major, rope'd
__device__ __half g_v16[NH * SEQ * HD];     // head-major
__device__ float  g_part[KSPLIT * NH * SEQ * HD];  // unnormalized partial O
__device__ float2 g_ml[KSPLIT * NH * SEQ];         // per-row (max, sum)

// ---------------------------------------------------------------------------
// helpers
// ---------------------------------------------------------------------------
__device__ __forceinline__ uint32_t h2_as_u32(__half2 h) {
    union { __half2 h2; uint32_t u; } cvt;
    cvt.h2 = h;
    return cvt.u;
}

__device__ __forceinline__ void mma_f16(float* d, const uint32_t* a, const uint32_t* b) {
    asm volatile(
        "mma.sync.aligned.m16n8k16.row.col.f32.f16.f16.f32 "
        "{%0,%1,%2,%3},{%4,%5,%6,%7},{%8,%9},{%0,%1,%2,%3};"
        : "+f"(d[0]), "+f"(d[1]), "+f"(d[2]), "+f"(d[3])
        : "r"(a[0]), "r"(a[1]), "r"(a[2]), "r"(a[3]),
          "r"(b[0]), "r"(b[1]));
}

__device__ __forceinline__ void ldsm_x4(uint32_t* r, uint32_t addr) {
    asm volatile("ldmatrix.sync.aligned.m8n8.x4.shared.b16 {%0,%1,%2,%3},[%4];"
        : "=r"(r[0]), "=r"(r[1]), "=r"(r[2]), "=r"(r[3]) : "r"(addr));
}

__device__ __forceinline__ void ldsm_x4_t(uint32_t* r, uint32_t addr) {
    asm volatile("ldmatrix.sync.aligned.m8n8.x4.trans.shared.b16 {%0,%1,%2,%3},[%4];"
        : "=r"(r[0]), "=r"(r[1]), "=r"(r[2]), "=r"(r[3]) : "r"(addr));
}

__device__ __forceinline__ void cp16(uint32_t dst, const void* src) {
    asm volatile("cp.async.ca.shared.global [%0], [%1], 16;" :: "r"(dst), "l"(src));
}
__device__ __forceinline__ void cp_commit() { asm volatile("cp.async.commit_group;"); }
__device__ __forceinline__ void cp_wait0() { asm volatile("cp.async.wait_group 0;"); }
__device__ __forceinline__ void cp_wait1() { asm volatile("cp.async.wait_group 1;"); }
__device__ __forceinline__ void cp_wait2() { asm volatile("cp.async.wait_group 2;"); }
__device__ __forceinline__ void cp_wait3() { asm volatile("cp.async.wait_group 3;"); }

// ---------------------------------------------------------------------------
// fp32 -> fp16 convert, 8 elems / thread
// ---------------------------------------------------------------------------
__global__ __launch_bounds__(256) void cvt_f2h(const float* __restrict__ src,
                                               __half* __restrict__ dst, int n8)
{
    int idx = blockIdx.x * blockDim.x + threadIdx.x;
    if (idx >= n8) return;
    float4 v0 = *reinterpret_cast<const float4*>(&src[idx * 8]);
    float4 v1 = *reinterpret_cast<const float4*>(&src[idx * 8 + 4]);
    __half2 h[4];
    h[0] = __floats2half2_rn(v0.x, v0.y);
    h[1] = __floats2half2_rn(v0.z, v0.w);
    h[2] = __floats2half2_rn(v1.x, v1.y);
    h[3] = __floats2half2_rn(v1.z, v1.w);
    *reinterpret_cast<uint4*>(&dst[idx * 8]) = *reinterpret_cast<uint4*>(h);
}

// ---------------------------------------------------------------------------
// HGEMM: C[M,N](fp32) = A[M,K](fp16) @ B[K,N](fp16) + bias[N](fp32)
// BM=128 BN=128 BK=32, 256 threads = 8 warps (2m x 4n), warp tile m64 x n32.
// 4-stage cp.async ring.
// ---------------------------------------------------------------------------
#define GLDA 40
#define GLDB 136
#define A_STG (128 * GLDA)
#define B_STG (32 * GLDB)
#define NSTG 4
#define HG_SMEM ((NSTG * (A_STG + B_STG)) * 2)

__global__ __launch_bounds__(256) void hgemm_bias(
    const __half* __restrict__ A, const __half* __restrict__ B,
    const float* __restrict__ bias, float* __restrict__ C,
    int M, int N, int K)
{
    extern __shared__ __half hsm[];
    __half* sA = hsm;
    __half* sB = hsm + NSTG * A_STG;

    const int tid  = threadIdx.x;
    const int wid  = tid >> 5;
    const int lane = tid & 31;
    const int wm   = wid >> 2;
    const int wn   = wid & 3;
    const int gid  = lane >> 2;
    const int tig  = lane & 3;
    const int j8   = lane & 7;
    const int grp  = lane >> 3;

    const int m0 = blockIdx.y * 128;
    const int n0 = blockIdx.x * 128;

    const uint32_t saBase = (uint32_t)__cvta_generic_to_shared(sA);
    const uint32_t sbBase = (uint32_t)__cvta_generic_to_shared(sB);

    const int aLane = ((grp & 1) * 8 + j8) * GLDA + (grp >> 1) * 8;
    const int bLane = ((grp & 1) * 8 + j8) * GLDB + (grp >> 1) * 8;

    float acc[4][4][4];
    #pragma unroll
    for (int i = 0; i < 4; i++)
        #pragma unroll
        for (int j = 0; j < 4; j++)
            #pragma unroll
            for (int c = 0; c < 4; c++) acc[i][j][c] = 0.f;

    const int NIT = K >> 5;

    auto load_tiles = [&](int stage, int k0) {
        #pragma unroll
        for (int s = 0; s < 2; s++) {
            int idx = tid + s * 256;
            int r = idx >> 2, q = idx & 3;
            uint32_t dst = saBase + (uint32_t)(stage * A_STG + r * GLDA + q * 8) * 2u;
            cp16(dst, &A[(m0 + r) * K + k0 + q * 8]);
        }
        #pragma unroll
        for (int s = 0; s < 2; s++) {
            int idx = tid + s * 256;
            int r = idx >> 4, q = idx & 15;
            uint32_t dst = sbBase + (uint32_t)(stage * B_STG + r * GLDB + q * 8) * 2u;
            cp16(dst, &B[(k0 + r) * N + n0 + q * 8]);
        }
    };

    load_tiles(0, 0);  cp_commit();
    load_tiles(1, 32); cp_commit();
    load_tiles(2, 64); cp_commit();

    for (int it = 0; it < NIT; it++) {
        if (it + 3 < NIT) {
            load_tiles((it + 3) & 3, (it + 3) << 5);
            cp_commit();
        }
        int rem = NIT - 1 - it;
        if (rem >= 3)      cp_wait3();
        else if (rem == 2) cp_wait2();
        else if (rem == 1) cp_wait1();
        else               cp_wait0();
        __syncthreads();

        const int stage = it & 3;
        const uint32_t aTile = saBase + (uint32_t)(stage * A_STG) * 2u;
        const uint32_t bTile = sbBase + (uint32_t)(stage * B_STG) * 2u;

        #pragma unroll
        for (int kk = 0; kk < 32; kk += 16) {
            uint32_t a[4][4];
            #pragma unroll
            for (int i = 0; i < 4; i++)
                ldsm_x4(a[i], aTile + (uint32_t)((wm * 64 + i * 16) * GLDA + kk + aLane) * 2u);
            uint32_t b4[2][4];
            #pragma unroll
            for (int jn = 0; jn < 2; jn++)
                ldsm_x4_t(b4[jn], bTile + (uint32_t)(kk * GLDB + wn * 32 + jn * 16 + bLane) * 2u);
            #pragma unroll
            for (int i = 0; i < 4; i++) {
                mma_f16(acc[i][0], a[i], b4[0]);
                mma_f16(acc[i][1], a[i], b4[0] + 2);
                mma_f16(acc[i][2], a[i], b4[1]);
                mma_f16(acc[i][3], a[i], b4[1] + 2);
            }
        }
        __syncthreads();
    }

    #pragma unroll
    for (int i = 0; i < 4; i++) {
        int r0 = m0 + wm * 64 + i * 16 + gid;
        #pragma unroll
        for (int j = 0; j < 4; j++) {
            int col = n0 + wn * 32 + j * 8 + 2 * tig;
            float bx = bias[col], by = bias[col + 1];
            float2 v0 = make_float2(acc[i][j][0] + bx, acc[i][j][1] + by);
            float2 v1 = make_float2(acc[i][j][2] + bx, acc[i][j][3] + by);
            *reinterpret_cast<float2*>(&C[r0 * N + col])       = v0;
            *reinterpret_cast<float2*>(&C[(r0 + 8) * N + col]) = v1;
        }
    }
}

// ---------------------------------------------------------------------------
// RoPE + fp16 convert for Q and K (head-major output). Q pre-scaled.
// ---------------------------------------------------------------------------
__global__ __launch_bounds__(256) void rope_cvt(const float* __restrict__ qkv,
                                                const int* __restrict__ pos)
{
    const int total = SEQ * 2 * NH * RD;
    int idx = blockIdx.x * blockDim.x + threadIdx.x;
    if (idx >= total) return;

    int d = idx % RD;
    int h = (idx / RD) % NH;
    int s = (idx / (RD * NH)) & 1;     // 0 = q, 1 = k
    int t = idx / (RD * NH * 2);

    int i = (d < 20) ? d : (d - 20);
    float p = (float)pos[t * 2 + ((d < 20) ? 0 : 1)];
    float ang = p * exp2f(-0.66438561897747246f * (float)i);
    float sv, cv;
    sincosf(ang, &sv, &cv);

    const float* src = &qkv[t * QKV_N + s * HIDDEN + h * HD];
    float x0 = src[d];
    float x1 = src[d + RD];
    float y0 = x0 * cv - x1 * sv;
    float y1 = x1 * cv + x0 * sv;

    float sc = s ? 1.0f : 0.11180339887498949f;   // q pre-scaled by 80^-0.5
    __half* dst = s ? g_k16 : g_q16;
    dst[(h * SEQ + t) * HD + d]      = __float2half(y0 * sc);
    dst[(h * SEQ + t) * HD + d + RD] = __float2half(y1 * sc);
}

// ---------------------------------------------------------------------------
// V fp16 convert (head-major).
// ---------------------------------------------------------------------------
__global__ __launch_bounds__(256) void v_cvt(const float* __restrict__ qkv)
{
    const int total = SEQ * NH * (HD / 4);
    int idx = blockIdx.x * blockDim.x + threadIdx.x;
    if (idx >= total) return;
    int c4 = idx % (HD / 4);
    int h  = (idx / (HD / 4)) % NH;
    int t  = idx / ((HD / 4) * NH);

    float4 v = *reinterpret_cast<const float4*>(
        &qkv[t * QKV_N + 2 * HIDDEN + h * HD + c4 * 4]);
    __half2* dst = reinterpret_cast<__half2*>(&g_v16[(h * SEQ + t) * HD + c4 * 4]);
    dst[0] = __floats2half2_rn(v.x, v.y);
    dst[1] = __floats2half2_rn(v.z, v.w);
}

// ---------------------------------------------------------------------------
// Flash attention, split-KV. Grid (SEQ/64, NH, KSPLIT), 128 threads.
// Each CTA does 1536 keys, writes unnormalized fp32 partials + (m,l).
// ---------------------------------------------------------------------------
#define LDH 88
#define KV_STG (64 * LDH)

__global__ __launch_bounds__(128, 4) void attn_kernel()
{
    __shared__ __half sK[2 * KV_STG];
    __shared__ __half sV[2 * KV_STG];

    const int h   = blockIdx.y;
    const int q0  = blockIdx.x * 64;
    const int z   = blockIdx.z;
    const int tid = threadIdx.x;
    const int w    = tid >> 5;
    const int lane = tid & 31;
    const int gid  = lane >> 2;
    const int tig  = lane & 3;
    const int j8   = lane & 7;
    const int grp  = lane >> 3;

    const uint32_t skBase = (uint32_t)__cvta_generic_to_shared(sK);
    const uint32_t svBase = (uint32_t)__cvta_generic_to_shared(sV);
    const int kOff = ((grp >> 1) * 8 + j8) * LDH + (grp & 1) * 8;
    const int vOff = ((grp & 1) * 8 + j8) * LDH + (grp >> 1) * 8;

    // ---- Stage Q via sK stage 0, extract register fragments ----
    {
        const __half* qg = &g_q16[(h * SEQ + q0) * HD];
        #pragma unroll
        for (int i = tid; i < 640; i += 128) {
            int r = i / 10, c = i % 10;
            *reinterpret_cast<uint4*>(&sK[r * LDH + c * 8]) =
                *reinterpret_cast<const uint4*>(&qg[r * HD + c * 8]);
        }
    }
    __syncthreads();

    uint32_t qa[5][4];
    const int qrow = 16 * w + gid;
    #pragma unroll
    for (int t = 0; t < 5; t++) {
        qa[t][0] = *reinterpret_cast<uint32_t*>(&sK[ qrow      * LDH + t * 16 + 2 * tig]);
        qa[t][1] = *reinterpret_cast<uint32_t*>(&sK[(qrow + 8) * LDH + t * 16 + 2 * tig]);
        qa[t][2] = *reinterpret_cast<uint32_t*>(&sK[ qrow      * LDH + t * 16 + 2 * tig + 8]);
        qa[t][3] = *reinterpret_cast<uint32_t*>(&sK[(qrow + 8) * LDH + t * 16 + 2 * tig + 8]);
    }
    __syncthreads();   // Q extraction done; sK stage 0 free for K tile

    auto load_kv = [&](int stage, int k0) {
        const __half* kg = &g_k16[(h * SEQ + k0) * HD];
        const __half* vg = &g_v16[(h * SEQ + k0) * HD];
        #pragma unroll
        for (int s = 0; s < 5; s++) {
            int idx = tid + s * 128;
            int r = idx / 10, c = idx % 10;
            uint32_t off = (uint32_t)(stage * KV_STG + r * LDH + c * 8) * 2u;
            cp16(skBase + off, &kg[r * HD + c * 8]);
            cp16(svBase + off, &vg[r * HD + c * 8]);
        }
    };

    const int NT   = SEQ / 64 / KSPLIT;    // 24 tiles per split
    const int kbeg = z * (SEQ / KSPLIT);   // starting key

    load_kv(0, kbeg);
    cp_commit();

    float m0r = -1e30f, m1r = -1e30f, l0 = 0.f, l1 = 0.f;
    float acc[10][4];
    #pragma unroll
    for (int n = 0; n < 10; n++)
        #pragma unroll
        for (int jj = 0; jj < 4; jj++) acc[n][jj] = 0.f;

    for (int kt = 0; kt < NT; kt++) {
        if (kt + 1 < NT) {
            load_kv((kt + 1) & 1, kbeg + (kt + 1) * 64);
            cp_commit();
            cp_wait1();
        } else {
            cp_wait0();
        }
        __syncthreads();

        const uint32_t kTile = skBase + (uint32_t)((kt & 1) * KV_STG) * 2u;
        const uint32_t vTile = svBase + (uint32_t)((kt & 1) * KV_STG) * 2u;

        // ---- S = Q @ K^T ----
        float sf[8][4];
        #pragma unroll
        for (int n = 0; n < 8; n++)
            #pragma unroll
            for (int jj = 0; jj < 4; jj++) sf[n][jj] = 0.f;

        #pragma unroll
        for (int t = 0; t < 5; t++) {
            #pragma unroll
            for (int np = 0; np < 4; np++) {
                uint32_t b[4];
                ldsm_x4(b, kTile + (uint32_t)(np * 16 * LDH + t * 16 + kOff) * 2u);
                mma_f16(sf[2 * np],     qa[t], b);
                mma_f16(sf[2 * np + 1], qa[t], b + 2);
            }
        }

        // ---- Online softmax ----
        float mx0 = -1e30f, mx1 = -1e30f;
        #pragma unroll
        for (int n = 0; n < 8; n++) {
            mx0 = fmaxf(mx0, fmaxf(sf[n][0], sf[n][1]));
            mx1 = fmaxf(mx1, fmaxf(sf[n][2], sf[n][3]));
        }
        #pragma unroll
        for (int o = 1; o <= 2; o <<= 1) {
            mx0 = fmaxf(mx0, __shfl_xor_sync(0xffffffffu, mx0, o));
            mx1 = fmaxf(mx1, __shfl_xor_sync(0xffffffffu, mx1, o));
        }
        float nm0 = fmaxf(m0r, mx0), nm1 = fmaxf(m1r, mx1);
        float c0 = __expf(m0r - nm0), c1 = __expf(m1r - nm1);
        m0r = nm0; m1r = nm1;

        float s0 = 0.f, s1 = 0.f;
        #pragma unroll
        for (int n = 0; n < 8; n++) {
            sf[n][0] = __expf(sf[n][0] - nm0);
            sf[n][1] = __expf(sf[n][1] - nm0);
            sf[n][2] = __expf(sf[n][2] - nm1);
            sf[n][3] = __expf(sf[n][3] - nm1);
            s0 += sf[n][0] + sf[n][1];
            s1 += sf[n][2] + sf[n][3];
        }
        #pragma unroll
        for (int o = 1; o <= 2; o <<= 1) {
            s0 += __shfl_xor_sync(0xffffffffu, s0, o);
            s1 += __shfl_xor_sync(0xffffffffu, s1, o);
        }
        l0 = l0 * c0 + s0;
        l1 = l1 * c1 + s1;
        #pragma unroll
        for (int n = 0; n < 10; n++) {
            acc[n][0] *= c0; acc[n][1] *= c0;
            acc[n][2] *= c1; acc[n][3] *= c1;
        }

        // ---- O += P @ V (register-resident P) ----
        #pragma unroll
        for (int s = 0; s < 4; s++) {
            uint32_t pa[4];
            pa[0] = h2_as_u32(__floats2half2_rn(sf[2*s][0],   sf[2*s][1]));
            pa[1] = h2_as_u32(__floats2half2_rn(sf[2*s][2],   sf[2*s][3]));
            pa[2] = h2_as_u32(__floats2half2_rn(sf[2*s+1][0], sf[2*s+1][1]));
            pa[3] = h2_as_u32(__floats2half2_rn(sf[2*s+1][2], sf[2*s+1][3]));
            #pragma unroll
            for (int np = 0; np < 5; np++) {
                uint32_t b[4];
                ldsm_x4_t(b, vTile + (uint32_t)(s * 16 * LDH + np * 16 + vOff) * 2u);
                mma_f16(acc[2 * np],     pa, b);
                mma_f16(acc[2 * np + 1], pa, b + 2);
            }
        }
        __syncthreads();
    }

    // ---- Epilogue: write unnormalized fp32 partials + (m, l) ----
    float* dst = &g_part[((z * NH + h) * SEQ + q0) * HD];
    #pragma unroll
    for (int n = 0; n < 10; n++) {
        int col = n * 8 + 2 * tig;
        *reinterpret_cast<float2*>(&dst[ qrow      * HD + col]) =
            make_float2(acc[n][0], acc[n][1]);
        *reinterpret_cast<float2*>(&dst[(qrow + 8) * HD + col]) =
            make_float2(acc[n][2], acc[n][3]);
    }
    if (tig == 0) {
        g_ml[(z * NH + h) * SEQ + q0 + qrow]     = make_float2(m0r, l0);
        g_ml[(z * NH + h) * SEQ + q0 + qrow + 8] = make_float2(m1r, l1);
    }
}

// ---------------------------------------------------------------------------
// Merge split-KV partials -> fp16 attention output [SEQ, HIDDEN]
// One thread per 2 output elems.
// ---------------------------------------------------------------------------
__global__ __launch_bounds__(256) void attn_merge()
{
    const int total = NH * SEQ * (HD / 2);
    int idx = blockIdx.x * blockDim.x + threadIdx.x;
    if (idx >= total) return;
    int d2 = idx % (HD / 2);
    int q  = (idx / (HD / 2)) % SEQ;
    int h  = idx / ((HD / 2) * SEQ);

    float2 ml0 = g_ml[(0 * NH + h) * SEQ + q];
    float2 ml1 = g_ml[(1 * NH + h) * SEQ + q];
    float M  = fmaxf(ml0.x, ml1.x);
    float w0 = __expf(ml0.x - M);
    float w1 = __expf(ml1.x - M);
    float inv = 1.0f / (ml0.y * w0 + ml1.y * w1);

    float2 p0 = *reinterpret_cast<const float2*>(
        &g_part[((0 * NH + h) * SEQ + q) * HD + 2 * d2]);
    float2 p1 = *reinterpret_cast<const float2*>(
        &g_part[((1 * NH + h) * SEQ + q) * HD + 2 * d2]);

    float ox = (p0.x * w0 + p1.x * w1) * inv;
    float oy = (p0.y * w0 + p1.y * w1) * inv;
    *reinterpret_cast<__half2*>(&g_att16[q * HIDDEN + h * HD + 2 * d2]) =
        __floats2half2_rn(ox, oy);
}

// ---------------------------------------------------------------------------
extern "C" void kernel_launch(void* const* d_in, const int* in_sizes, int n_in,
                              void* d_out, int out_size)
{
    const float* hs    = (const float*)d_in[0];
    const int*   pos   = (const int*)d_in[1];
    const float* qkv_w = (const float*)d_in[2];
    const float* qkv_b = (const float*)d_in[3];
    const float* o_w   = (const float*)d_in[4];
    const float* o_b   = (const float*)d_in[5];
    float* out = (float*)d_out;

    float*  qkv_ptr = nullptr;
    __half* hs16    = nullptr;
    __half* qw16    = nullptr;
    __half* ow16    = nullptr;
    __half* att16   = nullptr;
    cudaGetSymbolAddress((void**)&qkv_ptr, g_qkv);
    cudaGetSymbolAddress((void**)&hs16,    g_hs16);
    cudaGetSymbolAddress((void**)&qw16,    g_qw16);
    cudaGetSymbolAddress((void**)&ow16,    g_ow16);
    cudaGetSymbolAddress((void**)&att16,   g_att16);

    cudaFuncSetAttribute(hgemm_bias, cudaFuncAttributeMaxDynamicSharedMemorySize,
                         HG_SMEM);

    // 0) fp32 -> fp16 conversions
    {
        int n8 = SEQ * HIDDEN / 8;
        cvt_f2h<<<(n8 + 255) / 256, 256>>>(hs, hs16, n8);
        n8 = HIDDEN * QKV_N / 8;
        cvt_f2h<<<(n8 + 255) / 256, 256>>>(qkv_w, qw16, n8);
        n8 = HIDDEN * HIDDEN / 8;
        cvt_f2h<<<(n8 + 255) / 256, 256>>>(o_w, ow16, n8);
    }
    // 1) QKV GEMM + bias
    {
        dim3 grid(QKV_N / 128, SEQ / 128);  // (30, 24)
        hgemm_bias<<<grid, 256, HG_SMEM>>>(hs16, qw16, qkv_b, qkv_ptr, SEQ, QKV_N, HIDDEN);
    }
    // 2) RoPE + fp16 convert (q,k), fp16 convert (v)
    {
        int total = SEQ * 2 * NH * RD;
        rope_cvt<<<(total + 255) / 256, 256>>>(qkv_ptr, pos);
        int totv = SEQ * NH * (HD / 4);
        v_cvt<<<(totv + 255) / 256, 256>>>(qkv_ptr);
    }
    // 3) Attention, split-KV=2 + merge
    {
        dim3 grid(SEQ / 64, NH, KSPLIT);  // (48, 16, 2)
        attn_kernel<<<grid, 128>>>();
        int totm = NH * SEQ * (HD / 2);
        attn_merge<<<(totm + 255) / 256, 256>>>();
    }
    // 4) O GEMM + bias
    {
        dim3 grid(HIDDEN / 128, SEQ / 128);  // (10, 24)
        hgemm_bias<<<grid, 256, HG_SMEM>>>(att16, ow16, o_b, out, SEQ, HIDDEN, HIDDEN);
    }
}